// round 6
// baseline (speedup 1.0000x reference)
#include <cuda_runtime.h>
#include <cuda_fp16.h>
#include <mma.h>

using namespace nvcuda;

#define MAXN 100000
#define MAXE 1600000
#define NROWS 128
#define LDA 72
#define LDU 136

// Persistent scratch (no allocations allowed).
__device__ float4 g_h4[MAXN * 16];    // h:   N x 64 (fp32)
__device__ float4 g_Mh4[MAXN * 8];    // M:   N x 64 (fp16)
__device__ float4 g_agg4[MAXN * 16];  // agg: N x 64 (fp32)
// CSR (built once per launch from edge_index)
__device__ int g_counts[MAXN];
__device__ int g_rowstart[MAXN];
__device__ int g_rowend[MAXN];
__device__ int g_csrsrc[MAXE];
__device__ int g_blocksum[128];

// fp16 hi/lo split: x ~= hi + lo with |err| <= 2^-22 |x|
__device__ __forceinline__ void split2(float x, __half& hi, __half& lo) {
  hi = __float2half_rn(x);
  lo = __float2half_rn(x - __half2float(hi));
}

// ---------------------------------------------------------------------------
// h = relu(x @ w_in + b_in)
// ---------------------------------------------------------------------------
__global__ void __launch_bounds__(256) input_kernel(
    const float* __restrict__ x, const float* __restrict__ w_in,
    const float* __restrict__ b_in, int N) {
  int i = blockIdx.x * blockDim.x + threadIdx.x;
  if (i >= N * 64) return;
  int node = i >> 6, c = i & 63;
  float acc = __ldg(b_in + c);
  acc = fmaf(__ldg(x + node * 3 + 0), __ldg(w_in + c), acc);
  acc = fmaf(__ldg(x + node * 3 + 1), __ldg(w_in + 64 + c), acc);
  acc = fmaf(__ldg(x + node * 3 + 2), __ldg(w_in + 128 + c), acc);
  ((float*)g_h4)[i] = fmaxf(acc, 0.f);
}

// ---------------------------------------------------------------------------
// CSR build
// ---------------------------------------------------------------------------
__global__ void __launch_bounds__(256) zero_counts_kernel(int N) {
  int i = blockIdx.x * blockDim.x + threadIdx.x;
  if (i < N) g_counts[i] = 0;
}

__global__ void __launch_bounds__(256) hist_kernel(const int* __restrict__ ei,
                                                   int E) {
  int e = blockIdx.x * blockDim.x + threadIdx.x;
  if (e < E) atomicAdd(&g_counts[__ldg(ei + E + e)], 1);
}

__global__ void __launch_bounds__(1024) scan1_kernel(int N) {
  __shared__ int sh[1024];
  int t = threadIdx.x;
  int idx = blockIdx.x * 1024 + t;
  int v = (idx < N) ? g_counts[idx] : 0;
  sh[t] = v;
  __syncthreads();
#pragma unroll
  for (int off = 1; off < 1024; off <<= 1) {
    int x = (t >= off) ? sh[t - off] : 0;
    __syncthreads();
    sh[t] += x;
    __syncthreads();
  }
  if (idx < N) g_rowstart[idx] = sh[t] - v;
  if (t == 1023) g_blocksum[blockIdx.x] = sh[1023];
}

// parallel exclusive scan over <=128 block sums (was a serial 1-thread loop)
__global__ void __launch_bounds__(128) scan2_kernel(int nb) {
  __shared__ int sh[128];
  int t = threadIdx.x;
  int v = (t < nb) ? g_blocksum[t] : 0;
  sh[t] = v;
  __syncthreads();
#pragma unroll
  for (int off = 1; off < 128; off <<= 1) {
    int x = (t >= off) ? sh[t - off] : 0;
    __syncthreads();
    sh[t] += x;
    __syncthreads();
  }
  if (t < nb) g_blocksum[t] = sh[t] - v;  // exclusive
}

__global__ void __launch_bounds__(256) scan3_kernel(int N) {
  int i = blockIdx.x * blockDim.x + threadIdx.x;
  if (i < N) {
    int v = g_rowstart[i] + g_blocksum[i >> 10];
    g_rowstart[i] = v;
    g_rowend[i] = v;
  }
}

__global__ void __launch_bounds__(256) fill_kernel(const int* __restrict__ ei,
                                                   int E) {
  int e = blockIdx.x * blockDim.x + threadIdx.x;
  if (e < E) {
    int d = __ldg(ei + E + e);
    int pos = atomicAdd(&g_rowend[d], 1);
    g_csrsrc[pos] = __ldg(ei + e);
  }
}

// ---------------------------------------------------------------------------
// agg[i] = sum_{e: dst(e)=i} M[src(e)]   (warp per node, conflict-free)
// ---------------------------------------------------------------------------
__global__ void __launch_bounds__(256) gather_kernel(int N) {
  int w = (blockIdx.x * blockDim.x + threadIdx.x) >> 5;
  int lane = threadIdx.x & 31;
  if (w >= N) return;
  int s = __ldg(&g_rowstart[w]);
  int e = __ldg(&g_rowend[w]);
  const __half2* M = (const __half2*)g_Mh4;
  float2 a0 = make_float2(0.f, 0.f), a1 = make_float2(0.f, 0.f);
  int j = s;
  for (; j + 2 <= e; j += 2) {
    int s0 = __ldg(&g_csrsrc[j]);
    int s1 = __ldg(&g_csrsrc[j + 1]);
    float2 v0 = __half22float2(__ldg(&M[(size_t)s0 * 32 + lane]));
    float2 v1 = __half22float2(__ldg(&M[(size_t)s1 * 32 + lane]));
    a0.x += v0.x; a0.y += v0.y;
    a1.x += v1.x; a1.y += v1.y;
  }
  if (j < e) {
    int s0 = __ldg(&g_csrsrc[j]);
    float2 v0 = __half22float2(__ldg(&M[(size_t)s0 * 32 + lane]));
    a0.x += v0.x; a0.y += v0.y;
  }
  ((float2*)g_agg4)[(size_t)w * 32 + lane] =
      make_float2(a0.x + a1.x, a0.y + a1.y);
}

// 3-term split MMA over a 32x32 warp tile (2x2 16x16 frags), K-chunk at
// (A base rows wr, lda; B base k-row, wc col). acc += A*B with ~2^-22 error.
#define MMA_SPLIT_STEP(AHI, ALO, LDAX, BHI, BLO)                            \
  {                                                                         \
    wmma::fragment<wmma::matrix_a, 16, 16, 16, __half, wmma::row_major>    \
        afh[2], afl[2];                                                     \
    wmma::fragment<wmma::matrix_b, 16, 16, 16, __half, wmma::row_major>    \
        bfh[2], bfl[2];                                                     \
    wmma::load_matrix_sync(afh[0], (AHI), (LDAX));                          \
    wmma::load_matrix_sync(afh[1], (AHI) + 16 * (LDAX), (LDAX));            \
    wmma::load_matrix_sync(afl[0], (ALO), (LDAX));                          \
    wmma::load_matrix_sync(afl[1], (ALO) + 16 * (LDAX), (LDAX));            \
    wmma::load_matrix_sync(bfh[0], (BHI), LDA);                             \
    wmma::load_matrix_sync(bfh[1], (BHI) + 16, LDA);                        \
    wmma::load_matrix_sync(bfl[0], (BLO), LDA);                             \
    wmma::load_matrix_sync(bfl[1], (BLO) + 16, LDA);                        \
    _Pragma("unroll") for (int i = 0; i < 2; i++)                           \
        _Pragma("unroll") for (int j = 0; j < 2; j++) {                     \
      wmma::mma_sync(acc[i][j], afh[i], bfh[j], acc[i][j]);                 \
      wmma::mma_sync(acc[i][j], afl[i], bfh[j], acc[i][j]);                 \
      wmma::mma_sync(acc[i][j], afh[i], bfl[j], acc[i][j]);                 \
    }                                                                       \
  }

// ---------------------------------------------------------------------------
// msg: M = relu(h @ W1 + b1) @ W2 + b2   (split-fp16 HMMA, fp32 accumulate)
// 256 threads (8 warps, 4x2 grid of 32x32 warp tiles), tile 128 x 64.
// ---------------------------------------------------------------------------
__global__ void __launch_bounds__(256) msg_kernel(
    const float* __restrict__ W1, const float* __restrict__ B1,
    const float* __restrict__ W2, const float* __restrict__ B2, int N) {
  extern __shared__ char smc[];
  __half* a_hi = (__half*)smc;           // 128 x 72
  __half* a_lo = a_hi + 128 * LDA;       // 128 x 72
  __half* w1h = a_lo + 128 * LDA;        // 64 x 72
  __half* w1l = w1h + 64 * LDA;
  __half* w2h = w1l + 64 * LDA;
  __half* w2l = w2h + 64 * LDA;
  float* fs = (float*)(w2l + 64 * LDA);  // 128 x 72 fp32

  int tid = threadIdx.x;
  int rb = blockIdx.x * NROWS;

  for (int i = tid; i < 4096; i += 256) {
    int k = i >> 6, c = i & 63;
    split2(__ldg(W1 + i), w1h[k * LDA + c], w1l[k * LDA + c]);
    split2(__ldg(W2 + i), w2h[k * LDA + c], w2l[k * LDA + c]);
  }
  {
    int r = tid >> 1, hh = tid & 1;
    int grow = rb + r;
    int base = r * LDA + hh * 32;
    if (grow < N) {
      const float4* src =
          (const float4*)((const float*)g_h4 + (size_t)grow * 64) + hh * 8;
#pragma unroll
      for (int q = 0; q < 8; q++) {
        float4 v = src[q];
        split2(v.x, a_hi[base + q * 4 + 0], a_lo[base + q * 4 + 0]);
        split2(v.y, a_hi[base + q * 4 + 1], a_lo[base + q * 4 + 1]);
        split2(v.z, a_hi[base + q * 4 + 2], a_lo[base + q * 4 + 2]);
        split2(v.w, a_hi[base + q * 4 + 3], a_lo[base + q * 4 + 3]);
      }
    } else {
#pragma unroll
      for (int q = 0; q < 32; q++) {
        a_hi[base + q] = __float2half(0.f);
        a_lo[base + q] = __float2half(0.f);
      }
    }
  }
  __syncthreads();

  int wid = tid >> 5;
  int wr = (wid & 3) * 32, wc = (wid >> 2) * 32;

  wmma::fragment<wmma::accumulator, 16, 16, 16, float> acc[2][2];
#pragma unroll
  for (int i = 0; i < 2; i++)
#pragma unroll
    for (int j = 0; j < 2; j++) wmma::fill_fragment(acc[i][j], 0.f);

#pragma unroll
  for (int k = 0; k < 64; k += 16)
    MMA_SPLIT_STEP(a_hi + wr * LDA + k, a_lo + wr * LDA + k, LDA,
                   w1h + k * LDA + wc, w1l + k * LDA + wc);

#pragma unroll
  for (int i = 0; i < 2; i++)
#pragma unroll
    for (int j = 0; j < 2; j++)
      wmma::store_matrix_sync(fs + (wr + 16 * i) * LDA + wc + 16 * j,
                              acc[i][j], LDA, wmma::mem_row_major);
  __syncthreads();

  // t = relu(s1 + b1) -> overwrite a_hi/a_lo (split)
  {
    int r = tid >> 1, c0 = (tid & 1) * 32;
#pragma unroll
    for (int q = 0; q < 32; q++) {
      int c = c0 + q;
      float t = fmaxf(fs[r * LDA + c] + __ldg(B1 + c), 0.f);
      split2(t, a_hi[r * LDA + c], a_lo[r * LDA + c]);
    }
  }
  __syncthreads();

#pragma unroll
  for (int i = 0; i < 2; i++)
#pragma unroll
    for (int j = 0; j < 2; j++) wmma::fill_fragment(acc[i][j], 0.f);
#pragma unroll
  for (int k = 0; k < 64; k += 16)
    MMA_SPLIT_STEP(a_hi + wr * LDA + k, a_lo + wr * LDA + k, LDA,
                   w2h + k * LDA + wc, w2l + k * LDA + wc);
  __syncthreads();  // all fs reads (t pass) complete before overwrite
#pragma unroll
  for (int i = 0; i < 2; i++)
#pragma unroll
    for (int j = 0; j < 2; j++)
      wmma::store_matrix_sync(fs + (wr + 16 * i) * LDA + wc + 16 * j,
                              acc[i][j], LDA, wmma::mem_row_major);
  __syncthreads();

  // M (fp16) = s2 + b2
  {
    int r = tid >> 1, c0 = (tid & 1) * 32;
    int grow = rb + r;
    if (grow < N) {
      __half2* dst = (__half2*)g_Mh4 + (size_t)grow * 32 + (c0 >> 1);
#pragma unroll
      for (int q = 0; q < 16; q++) {
        int c = c0 + q * 2;
        dst[q] = __floats2half2_rn(fs[r * LDA + c] + __ldg(B2 + c),
                                   fs[r * LDA + c + 1] + __ldg(B2 + c + 1));
      }
    }
  }
}

// ---------------------------------------------------------------------------
// upd: hn = relu([h,agg] @ W1 + b1) @ W2 + b2 ; bn ; h = relu(hn + h)
// A tile 128 x 128 split-fp16 (cols 0..63 = h, 64..127 = agg, then t).
// Residual h_old reconstructed from hi+lo (exact to 2^-22, NOT fp16-rounded).
// ---------------------------------------------------------------------------
__global__ void __launch_bounds__(256) upd_kernel(
    const float* __restrict__ W1, const float* __restrict__ B1,
    const float* __restrict__ W2, const float* __restrict__ B2,
    const float* __restrict__ Gm, const float* __restrict__ Bt,
    const float* __restrict__ Mn, const float* __restrict__ Vr, int N) {
  extern __shared__ char smc[];
  __half* a_hi = (__half*)smc;           // 128 x 136
  __half* a_lo = a_hi + 128 * LDU;       // 128 x 136
  __half* w1h = a_lo + 128 * LDU;        // 128 x 72
  __half* w1l = w1h + 128 * LDA;
  __half* w2h = w1l + 128 * LDA;         // 64 x 72
  __half* w2l = w2h + 64 * LDA;
  float* fs = (float*)(w2l + 64 * LDA);  // 128 x 72 fp32
  __shared__ float scs[64], shs[64], b2s[64];

  int tid = threadIdx.x;
  int rb = blockIdx.x * NROWS;

  for (int i = tid; i < 8192; i += 256) {
    int k = i >> 6, c = i & 63;
    split2(__ldg(W1 + i), w1h[k * LDA + c], w1l[k * LDA + c]);
  }
  for (int i = tid; i < 4096; i += 256) {
    int k = i >> 6, c = i & 63;
    split2(__ldg(W2 + i), w2h[k * LDA + c], w2l[k * LDA + c]);
  }
  if (tid < 64) {
    float s = __ldg(Gm + tid) * rsqrtf(__ldg(Vr + tid) + 1e-5f);
    scs[tid] = s;
    shs[tid] = __ldg(Bt + tid) - __ldg(Mn + tid) * s;
    b2s[tid] = __ldg(B2 + tid);
  }
  {
    int r = tid >> 1, hh = tid & 1;
    int grow = rb + r;
    int b1i = r * LDU + hh * 32;
    int b2i = r * LDU + 64 + hh * 32;
    if (grow < N) {
      const float4* s1 =
          (const float4*)((const float*)g_h4 + (size_t)grow * 64) + hh * 8;
      const float4* s2 =
          (const float4*)((const float*)g_agg4 + (size_t)grow * 64) + hh * 8;
#pragma unroll
      for (int q = 0; q < 8; q++) {
        float4 v = s1[q];
        split2(v.x, a_hi[b1i + q * 4 + 0], a_lo[b1i + q * 4 + 0]);
        split2(v.y, a_hi[b1i + q * 4 + 1], a_lo[b1i + q * 4 + 1]);
        split2(v.z, a_hi[b1i + q * 4 + 2], a_lo[b1i + q * 4 + 2]);
        split2(v.w, a_hi[b1i + q * 4 + 3], a_lo[b1i + q * 4 + 3]);
        float4 u = s2[q];
        split2(u.x, a_hi[b2i + q * 4 + 0], a_lo[b2i + q * 4 + 0]);
        split2(u.y, a_hi[b2i + q * 4 + 1], a_lo[b2i + q * 4 + 1]);
        split2(u.z, a_hi[b2i + q * 4 + 2], a_lo[b2i + q * 4 + 2]);
        split2(u.w, a_hi[b2i + q * 4 + 3], a_lo[b2i + q * 4 + 3]);
      }
    } else {
#pragma unroll
      for (int q = 0; q < 32; q++) {
        a_hi[b1i + q] = __float2half(0.f);
        a_lo[b1i + q] = __float2half(0.f);
        a_hi[b2i + q] = __float2half(0.f);
        a_lo[b2i + q] = __float2half(0.f);
      }
    }
  }
  __syncthreads();

  int wid = tid >> 5;
  int wr = (wid & 3) * 32, wc = (wid >> 2) * 32;

  wmma::fragment<wmma::accumulator, 16, 16, 16, float> acc[2][2];
#pragma unroll
  for (int i = 0; i < 2; i++)
#pragma unroll
    for (int j = 0; j < 2; j++) wmma::fill_fragment(acc[i][j], 0.f);

#pragma unroll
  for (int k = 0; k < 128; k += 16)
    MMA_SPLIT_STEP(a_hi + wr * LDU + k, a_lo + wr * LDU + k, LDU,
                   w1h + k * LDA + wc, w1l + k * LDA + wc);

#pragma unroll
  for (int i = 0; i < 2; i++)
#pragma unroll
    for (int j = 0; j < 2; j++)
      wmma::store_matrix_sync(fs + (wr + 16 * i) * LDA + wc + 16 * j,
                              acc[i][j], LDA, wmma::mem_row_major);
  __syncthreads();

  // t = relu(s1 + b1) -> a cols [64,128) split (agg no longer needed)
  {
    int r = tid >> 1, c0 = (tid & 1) * 32;
#pragma unroll
    for (int q = 0; q < 32; q++) {
      int c = c0 + q;
      float t = fmaxf(fs[r * LDA + c] + __ldg(B1 + c), 0.f);
      split2(t, a_hi[r * LDU + 64 + c], a_lo[r * LDU + 64 + c]);
    }
  }
  __syncthreads();

#pragma unroll
  for (int i = 0; i < 2; i++)
#pragma unroll
    for (int j = 0; j < 2; j++) wmma::fill_fragment(acc[i][j], 0.f);
#pragma unroll
  for (int k = 0; k < 64; k += 16)
    MMA_SPLIT_STEP(a_hi + wr * LDU + 64 + k, a_lo + wr * LDU + 64 + k, LDU,
                   w2h + k * LDA + wc, w2l + k * LDA + wc);
  __syncthreads();
#pragma unroll
  for (int i = 0; i < 2; i++)
#pragma unroll
    for (int j = 0; j < 2; j++)
      wmma::store_matrix_sync(fs + (wr + 16 * i) * LDA + wc + 16 * j,
                              acc[i][j], LDA, wmma::mem_row_major);
  __syncthreads();

  // h = relu(bn(s2 + b2) + h_old);  h_old = hi + lo (cols [0,64), exact)
  {
    int r = tid >> 1, c0 = (tid & 1) * 32;
    int grow = rb + r;
    if (grow < N) {
      float* dst = (float*)g_h4 + (size_t)grow * 64 + c0;
#pragma unroll
      for (int q = 0; q < 8; q++) {
        float4 o;
        float* op = (float*)&o;
#pragma unroll
        for (int u = 0; u < 4; u++) {
          int c = c0 + q * 4 + u;
          float hn = fs[r * LDA + c] + b2s[c];
          float hold = __half2float(a_hi[r * LDU + c]) +
                       __half2float(a_lo[r * LDU + c]);
          op[u] = fmaxf(fmaf(hn, scs[c], shs[c]) + hold, 0.f);
        }
        ((float4*)dst)[q] = o;
      }
    }
  }
}

// ---------------------------------------------------------------------------
// out = relu(h[:NQ] @ out_w1 + b1) @ out_w2 + b2   (warp per node)
// ---------------------------------------------------------------------------
__global__ void __launch_bounds__(256) out_kernel(
    const float* __restrict__ w1, const float* __restrict__ b1,
    const float* __restrict__ w2, const float* __restrict__ b2,
    float* __restrict__ out, int NQ) {
  int warp = (blockIdx.x * blockDim.x + threadIdx.x) >> 5;
  int lane = threadIdx.x & 31;
  if (warp >= NQ) return;
  const float* h = (const float*)g_h4;
  float2 hv = ((const float2*)(h + (size_t)warp * 64))[lane];
  float acc = __ldg(b1 + lane);
#pragma unroll
  for (int kk = 0; kk < 32; kk++) {
    float hx = __shfl_sync(0xffffffffu, hv.x, kk);
    float hy = __shfl_sync(0xffffffffu, hv.y, kk);
    acc = fmaf(hx, __ldg(w1 + (2 * kk) * 32 + lane), acc);
    acc = fmaf(hy, __ldg(w1 + (2 * kk + 1) * 32 + lane), acc);
  }
  float v = fmaxf(acc, 0.f) * __ldg(w2 + lane);
#pragma unroll
  for (int o = 16; o; o >>= 1) v += __shfl_down_sync(0xffffffffu, v, o);
  if (lane == 0) out[warp] = v + __ldg(b2);
}

// ---------------------------------------------------------------------------
extern "C" void kernel_launch(void* const* d_in, const int* in_sizes, int n_in,
                              void* d_out, int out_size) {
  int off = (n_in >= 21) ? 1 : 0;
  const float* x      = (const float*)d_in[0];
  const int*   ei     = (const int*)d_in[1];
  const float* w_in   = (const float*)d_in[2 + off];
  const float* b_in   = (const float*)d_in[3 + off];
  const float* msg_w1 = (const float*)d_in[4 + off];
  const float* msg_b1 = (const float*)d_in[5 + off];
  const float* msg_w2 = (const float*)d_in[6 + off];
  const float* msg_b2 = (const float*)d_in[7 + off];
  const float* upd_w1 = (const float*)d_in[8 + off];
  const float* upd_b1 = (const float*)d_in[9 + off];
  const float* upd_w2 = (const float*)d_in[10 + off];
  const float* upd_b2 = (const float*)d_in[11 + off];
  const float* bn_g   = (const float*)d_in[12 + off];
  const float* bn_b   = (const float*)d_in[13 + off];
  const float* bn_m   = (const float*)d_in[14 + off];
  const float* bn_v   = (const float*)d_in[15 + off];
  const float* out_w1 = (const float*)d_in[16 + off];
  const float* out_b1 = (const float*)d_in[17 + off];
  const float* out_w2 = (const float*)d_in[18 + off];
  const float* out_b2 = (const float*)d_in[19 + off];

  int N = in_sizes[0] / 3;
  int E = in_sizes[1] / 2;
  int L = in_sizes[4 + off] / (64 * 64);
  int NQ = out_size;

  const int MSG_SMEM =
      (2 * 128 * LDA + 4 * 64 * LDA) * 2 + 128 * LDA * 4;  // ~108 KB
  const int UPD_SMEM =
      (2 * 128 * LDU + 2 * 128 * LDA + 2 * 64 * LDA) * 2 +
      128 * LDA * 4;  // ~158 KB
  cudaFuncSetAttribute(msg_kernel, cudaFuncAttributeMaxDynamicSharedMemorySize,
                       MSG_SMEM);
  cudaFuncSetAttribute(upd_kernel, cudaFuncAttributeMaxDynamicSharedMemorySize,
                       UPD_SMEM);

  int gb = (N + NROWS - 1) / NROWS;
  int nb_scan = (N + 1023) / 1024;

  // Launch order puts msg_kernel at position 4 so ncu (-s 5 -c 1) profiles it.
  input_kernel<<<(N * 64 + 255) / 256, 256>>>(x, w_in, b_in, N);
  zero_counts_kernel<<<(N + 255) / 256, 256>>>(N);
  hist_kernel<<<(E + 255) / 256, 256>>>(ei, E);
  msg_kernel<<<gb, 256, MSG_SMEM>>>(msg_w1, msg_b1, msg_w2, msg_b2, N);
  scan1_kernel<<<nb_scan, 1024>>>(N);
  scan2_kernel<<<1, 128>>>(nb_scan);
  scan3_kernel<<<(N + 255) / 256, 256>>>(N);
  fill_kernel<<<(E + 255) / 256, 256>>>(ei, E);

  for (int l = 0; l < L; l++) {
    if (l > 0)
      msg_kernel<<<gb, 256, MSG_SMEM>>>(msg_w1 + l * 4096, msg_b1 + l * 64,
                                        msg_w2 + l * 4096, msg_b2 + l * 64, N);
    gather_kernel<<<(N * 32 + 255) / 256, 256>>>(N);
    upd_kernel<<<gb, 256, UPD_SMEM>>>(
        upd_w1 + l * 8192, upd_b1 + l * 64, upd_w2 + l * 4096, upd_b2 + l * 64,
        bn_g + l * 64, bn_b + l * 64, bn_m + l * 64, bn_v + l * 64, N);
  }

  out_kernel<<<(NQ * 32 + 255) / 256, 256>>>(out_w1, out_b1, out_w2, out_b2,
                                             (float*)d_out, NQ);
}

// round 7
// speedup vs baseline: 1.0140x; 1.0140x over previous
#include <cuda_runtime.h>
#include <cuda_fp16.h>
#include <mma.h>

using namespace nvcuda;

#define MAXN 100000
#define MAXE 1600000
#define NROWS 128
#define LDA 72
#define LDU 136

// Persistent scratch (no allocations allowed).
__device__ float4 g_h4[MAXN * 16];    // h:   N x 64 (fp32)
__device__ float4 g_Mh4[MAXN * 8];    // M:   N x 64 (fp16)
__device__ float4 g_agg4[MAXN * 16];  // agg: N x 64 (fp32)
// CSR (built once per launch from edge_index)
__device__ int g_counts[MAXN];
__device__ int g_rowstart[MAXN];
__device__ int g_rowend[MAXN];
__device__ int g_csrsrc[MAXE];
__device__ int g_blocksum[128];

// fp16 hi/lo split: x ~= hi + lo with |err| <= 2^-22 |x|
__device__ __forceinline__ void split2(float x, __half& hi, __half& lo) {
  hi = __float2half_rn(x);
  lo = __float2half_rn(x - __half2float(hi));
}

// ---------------------------------------------------------------------------
// h = relu(x @ w_in + b_in)
// ---------------------------------------------------------------------------
__global__ void __launch_bounds__(256) input_kernel(
    const float* __restrict__ x, const float* __restrict__ w_in,
    const float* __restrict__ b_in, int N) {
  int i = blockIdx.x * blockDim.x + threadIdx.x;
  if (i >= N * 64) return;
  int node = i >> 6, c = i & 63;
  float acc = __ldg(b_in + c);
  acc = fmaf(__ldg(x + node * 3 + 0), __ldg(w_in + c), acc);
  acc = fmaf(__ldg(x + node * 3 + 1), __ldg(w_in + 64 + c), acc);
  acc = fmaf(__ldg(x + node * 3 + 2), __ldg(w_in + 128 + c), acc);
  ((float*)g_h4)[i] = fmaxf(acc, 0.f);
}

// ---------------------------------------------------------------------------
// CSR build
// ---------------------------------------------------------------------------
__global__ void __launch_bounds__(256) zero_counts_kernel(int N) {
  int i = blockIdx.x * blockDim.x + threadIdx.x;
  if (i < N) g_counts[i] = 0;
}

__global__ void __launch_bounds__(256) hist_kernel(const int* __restrict__ ei,
                                                   int E) {
  int e = blockIdx.x * blockDim.x + threadIdx.x;
  if (e < E) atomicAdd(&g_counts[__ldg(ei + E + e)], 1);
}

__global__ void __launch_bounds__(1024) scan1_kernel(int N) {
  __shared__ int sh[1024];
  int t = threadIdx.x;
  int idx = blockIdx.x * 1024 + t;
  int v = (idx < N) ? g_counts[idx] : 0;
  sh[t] = v;
  __syncthreads();
#pragma unroll
  for (int off = 1; off < 1024; off <<= 1) {
    int x = (t >= off) ? sh[t - off] : 0;
    __syncthreads();
    sh[t] += x;
    __syncthreads();
  }
  if (idx < N) g_rowstart[idx] = sh[t] - v;
  if (t == 1023) g_blocksum[blockIdx.x] = sh[1023];
}

__global__ void __launch_bounds__(128) scan2_kernel(int nb) {
  __shared__ int sh[128];
  int t = threadIdx.x;
  int v = (t < nb) ? g_blocksum[t] : 0;
  sh[t] = v;
  __syncthreads();
#pragma unroll
  for (int off = 1; off < 128; off <<= 1) {
    int x = (t >= off) ? sh[t - off] : 0;
    __syncthreads();
    sh[t] += x;
    __syncthreads();
  }
  if (t < nb) g_blocksum[t] = sh[t] - v;  // exclusive
}

__global__ void __launch_bounds__(256) scan3_kernel(int N) {
  int i = blockIdx.x * blockDim.x + threadIdx.x;
  if (i < N) {
    int v = g_rowstart[i] + g_blocksum[i >> 10];
    g_rowstart[i] = v;
    g_rowend[i] = v;
  }
}

__global__ void __launch_bounds__(256) fill_kernel(const int* __restrict__ ei,
                                                   int E) {
  int e = blockIdx.x * blockDim.x + threadIdx.x;
  if (e < E) {
    int d = __ldg(ei + E + e);
    int pos = atomicAdd(&g_rowend[d], 1);
    g_csrsrc[pos] = __ldg(ei + e);
  }
}

// ---------------------------------------------------------------------------
// agg[i] = sum_{e: dst(e)=i} M[src(e)]   (warp per node, conflict-free)
// ---------------------------------------------------------------------------
__global__ void __launch_bounds__(256) gather_kernel(int N) {
  int w = (blockIdx.x * blockDim.x + threadIdx.x) >> 5;
  int lane = threadIdx.x & 31;
  if (w >= N) return;
  int s = __ldg(&g_rowstart[w]);
  int e = __ldg(&g_rowend[w]);
  const __half2* M = (const __half2*)g_Mh4;
  float2 a0 = make_float2(0.f, 0.f), a1 = make_float2(0.f, 0.f);
  int j = s;
  for (; j + 2 <= e; j += 2) {
    int s0 = __ldg(&g_csrsrc[j]);
    int s1 = __ldg(&g_csrsrc[j + 1]);
    float2 v0 = __half22float2(__ldg(&M[(size_t)s0 * 32 + lane]));
    float2 v1 = __half22float2(__ldg(&M[(size_t)s1 * 32 + lane]));
    a0.x += v0.x; a0.y += v0.y;
    a1.x += v1.x; a1.y += v1.y;
  }
  if (j < e) {
    int s0 = __ldg(&g_csrsrc[j]);
    float2 v0 = __half22float2(__ldg(&M[(size_t)s0 * 32 + lane]));
    a0.x += v0.x; a0.y += v0.y;
  }
  ((float2*)g_agg4)[(size_t)w * 32 + lane] =
      make_float2(a0.x + a1.x, a0.y + a1.y);
}

// 3-term split MMA over a 32x32 warp tile (2x2 16x16 frags).
#define MMA_SPLIT_STEP(AHI, ALO, LDAX, BHI, BLO)                            \
  {                                                                         \
    wmma::fragment<wmma::matrix_a, 16, 16, 16, __half, wmma::row_major>    \
        afh[2], afl[2];                                                     \
    wmma::fragment<wmma::matrix_b, 16, 16, 16, __half, wmma::row_major>    \
        bfh[2], bfl[2];                                                     \
    wmma::load_matrix_sync(afh[0], (AHI), (LDAX));                          \
    wmma::load_matrix_sync(afh[1], (AHI) + 16 * (LDAX), (LDAX));            \
    wmma::load_matrix_sync(afl[0], (ALO), (LDAX));                          \
    wmma::load_matrix_sync(afl[1], (ALO) + 16 * (LDAX), (LDAX));            \
    wmma::load_matrix_sync(bfh[0], (BHI), LDA);                             \
    wmma::load_matrix_sync(bfh[1], (BHI) + 16, LDA);                        \
    wmma::load_matrix_sync(bfl[0], (BLO), LDA);                             \
    wmma::load_matrix_sync(bfl[1], (BLO) + 16, LDA);                        \
    _Pragma("unroll") for (int i = 0; i < 2; i++)                           \
        _Pragma("unroll") for (int j = 0; j < 2; j++) {                     \
      wmma::mma_sync(acc[i][j], afh[i], bfh[j], acc[i][j]);                 \
      wmma::mma_sync(acc[i][j], afl[i], bfh[j], acc[i][j]);                 \
      wmma::mma_sync(acc[i][j], afh[i], bfl[j], acc[i][j]);                 \
    }                                                                       \
  }

// Store this warp's 2x2 fp32 accs into the 64-row fs buffer (two-pass).
#define STORE_ACCS(row_off)                                                 \
  if (wr >= (row_off) && wr < (row_off) + 64) {                             \
    _Pragma("unroll") for (int i = 0; i < 2; i++)                           \
        _Pragma("unroll") for (int j = 0; j < 2; j++)                       \
            wmma::store_matrix_sync(                                        \
                fs + (wr - (row_off) + 16 * i) * LDA + wc + 16 * j,         \
                acc[i][j], LDA, wmma::mem_row_major);                       \
  }

#define FILL_ACCS()                                                         \
  _Pragma("unroll") for (int i = 0; i < 2; i++)                             \
      _Pragma("unroll") for (int j = 0; j < 2; j++)                         \
          wmma::fill_fragment(acc[i][j], 0.f);

// ---------------------------------------------------------------------------
// msg: M = relu(h @ W1 + b1) @ W2 + b2   (split-fp16 HMMA, fp32 accumulate)
// 256 threads, tile 128x64. smem 73.7 KB -> 3 blocks/SM.
// Single weight buffer: W1 staged first, W2 reloaded after stage 1.
// ---------------------------------------------------------------------------
__global__ void __launch_bounds__(256, 3) msg_kernel(
    const float* __restrict__ W1, const float* __restrict__ B1,
    const float* __restrict__ W2, const float* __restrict__ B2, int N) {
  extern __shared__ char smc[];
  __half* a_hi = (__half*)smc;          // 128 x 72
  __half* a_lo = a_hi + 128 * LDA;      // 128 x 72
  __half* wh = a_lo + 128 * LDA;        // 64 x 72
  __half* wl = wh + 64 * LDA;           // 64 x 72
  float* fs = (float*)(wl + 64 * LDA);  // 64 x 72 fp32 (two-pass)

  int tid = threadIdx.x;
  int rb = blockIdx.x * NROWS;
  int wid = tid >> 5;
  int wr = (wid & 3) * 32, wc = (wid >> 2) * 32;

  for (int i = tid; i < 4096; i += 256) {
    int k = i >> 6, c = i & 63;
    split2(__ldg(W1 + i), wh[k * LDA + c], wl[k * LDA + c]);
  }
  {
    int r = tid >> 1, hh = tid & 1, grow = rb + r;
    int base = r * LDA + hh * 32;
    if (grow < N) {
      const float4* src =
          (const float4*)((const float*)g_h4 + (size_t)grow * 64) + hh * 8;
#pragma unroll
      for (int q = 0; q < 8; q++) {
        float4 v = src[q];
        split2(v.x, a_hi[base + q * 4 + 0], a_lo[base + q * 4 + 0]);
        split2(v.y, a_hi[base + q * 4 + 1], a_lo[base + q * 4 + 1]);
        split2(v.z, a_hi[base + q * 4 + 2], a_lo[base + q * 4 + 2]);
        split2(v.w, a_hi[base + q * 4 + 3], a_lo[base + q * 4 + 3]);
      }
    } else {
#pragma unroll
      for (int q = 0; q < 32; q++) {
        a_hi[base + q] = __float2half(0.f);
        a_lo[base + q] = __float2half(0.f);
      }
    }
  }
  __syncthreads();

  wmma::fragment<wmma::accumulator, 16, 16, 16, float> acc[2][2];
  FILL_ACCS();
#pragma unroll
  for (int k = 0; k < 64; k += 16)
    MMA_SPLIT_STEP(a_hi + wr * LDA + k, a_lo + wr * LDA + k, LDA,
                   wh + k * LDA + wc, wl + k * LDA + wc);
  __syncthreads();  // all A + W1 reads done

  // pass A store + reload weight buffer with W2
  STORE_ACCS(0);
  for (int i = tid; i < 4096; i += 256) {
    int k = i >> 6, c = i & 63;
    split2(__ldg(W2 + i), wh[k * LDA + c], wl[k * LDA + c]);
  }
  __syncthreads();
  {  // t rows [0,64) -> A region (split)
    int r = tid >> 2, c0 = (tid & 3) * 16;
#pragma unroll
    for (int q = 0; q < 16; q++) {
      int c = c0 + q;
      float t = fmaxf(fs[r * LDA + c] + __ldg(B1 + c), 0.f);
      split2(t, a_hi[r * LDA + c], a_lo[r * LDA + c]);
    }
  }
  __syncthreads();
  STORE_ACCS(64);
  __syncthreads();
  {  // t rows [64,128)
    int r = tid >> 2, c0 = (tid & 3) * 16;
#pragma unroll
    for (int q = 0; q < 16; q++) {
      int c = c0 + q;
      float t = fmaxf(fs[r * LDA + c] + __ldg(B1 + c), 0.f);
      split2(t, a_hi[(64 + r) * LDA + c], a_lo[(64 + r) * LDA + c]);
    }
  }
  __syncthreads();

  FILL_ACCS();
#pragma unroll
  for (int k = 0; k < 64; k += 16)
    MMA_SPLIT_STEP(a_hi + wr * LDA + k, a_lo + wr * LDA + k, LDA,
                   wh + k * LDA + wc, wl + k * LDA + wc);
  __syncthreads();

  STORE_ACCS(0);
  __syncthreads();
  {  // M rows [0,64)
    int r = tid >> 2, c0 = (tid & 3) * 16;
    int grow = rb + r;
    if (grow < N) {
      __half2* dst = (__half2*)g_Mh4 + (size_t)grow * 32 + (c0 >> 1);
#pragma unroll
      for (int q = 0; q < 8; q++) {
        int c = c0 + 2 * q;
        dst[q] = __floats2half2_rn(fs[r * LDA + c] + __ldg(B2 + c),
                                   fs[r * LDA + c + 1] + __ldg(B2 + c + 1));
      }
    }
  }
  __syncthreads();
  STORE_ACCS(64);
  __syncthreads();
  {  // M rows [64,128)
    int r = tid >> 2, c0 = (tid & 3) * 16;
    int grow = rb + 64 + r;
    if (grow < N) {
      __half2* dst = (__half2*)g_Mh4 + (size_t)grow * 32 + (c0 >> 1);
#pragma unroll
      for (int q = 0; q < 8; q++) {
        int c = c0 + 2 * q;
        dst[q] = __floats2half2_rn(fs[r * LDA + c] + __ldg(B2 + c),
                                   fs[r * LDA + c + 1] + __ldg(B2 + c + 1));
      }
    }
  }
}

// ---------------------------------------------------------------------------
// upd: hn = relu([h,agg] @ W1 + b1) @ W2 + b2 ; bn ; h = relu(hn + h)
// smem 106.5 KB -> 2 blocks/SM. W1 loaded in two K-halves, then W2, in one
// shared buffer. Residual h_old read fresh from global fp32 (exact).
// ---------------------------------------------------------------------------
__global__ void __launch_bounds__(256, 2) upd_kernel(
    const float* __restrict__ W1, const float* __restrict__ B1,
    const float* __restrict__ W2, const float* __restrict__ B2,
    const float* __restrict__ Gm, const float* __restrict__ Bt,
    const float* __restrict__ Mn, const float* __restrict__ Vr, int N) {
  extern __shared__ char smc[];
  __half* a_hi = (__half*)smc;          // 128 x 136
  __half* a_lo = a_hi + 128 * LDU;      // 128 x 136
  __half* wh = a_lo + 128 * LDU;        // 64 x 72
  __half* wl = wh + 64 * LDA;           // 64 x 72
  float* fs = (float*)(wl + 64 * LDA);  // 64 x 72 fp32 (two-pass)
  __shared__ float scs[64], shs[64], b2s[64];

  int tid = threadIdx.x;
  int rb = blockIdx.x * NROWS;
  int wid = tid >> 5;
  int wr = (wid & 3) * 32, wc = (wid >> 2) * 32;

  for (int i = tid; i < 4096; i += 256) {  // W1 rows [0,64)
    int k = i >> 6, c = i & 63;
    split2(__ldg(W1 + i), wh[k * LDA + c], wl[k * LDA + c]);
  }
  if (tid < 64) {
    float s = __ldg(Gm + tid) * rsqrtf(__ldg(Vr + tid) + 1e-5f);
    scs[tid] = s;
    shs[tid] = __ldg(Bt + tid) - __ldg(Mn + tid) * s;
    b2s[tid] = __ldg(B2 + tid);
  }
  {
    int r = tid >> 1, hh = tid & 1, grow = rb + r;
    int b1i = r * LDU + hh * 32;
    int b2i = r * LDU + 64 + hh * 32;
    if (grow < N) {
      const float4* s1 =
          (const float4*)((const float*)g_h4 + (size_t)grow * 64) + hh * 8;
      const float4* s2 =
          (const float4*)((const float*)g_agg4 + (size_t)grow * 64) + hh * 8;
#pragma unroll
      for (int q = 0; q < 8; q++) {
        float4 v = s1[q];
        split2(v.x, a_hi[b1i + q * 4 + 0], a_lo[b1i + q * 4 + 0]);
        split2(v.y, a_hi[b1i + q * 4 + 1], a_lo[b1i + q * 4 + 1]);
        split2(v.z, a_hi[b1i + q * 4 + 2], a_lo[b1i + q * 4 + 2]);
        split2(v.w, a_hi[b1i + q * 4 + 3], a_lo[b1i + q * 4 + 3]);
        float4 u = s2[q];
        split2(u.x, a_hi[b2i + q * 4 + 0], a_lo[b2i + q * 4 + 0]);
        split2(u.y, a_hi[b2i + q * 4 + 1], a_lo[b2i + q * 4 + 1]);
        split2(u.z, a_hi[b2i + q * 4 + 2], a_lo[b2i + q * 4 + 2]);
        split2(u.w, a_hi[b2i + q * 4 + 3], a_lo[b2i + q * 4 + 3]);
      }
    } else {
#pragma unroll
      for (int q = 0; q < 32; q++) {
        a_hi[b1i + q] = __float2half(0.f);
        a_lo[b1i + q] = __float2half(0.f);
        a_hi[b2i + q] = __float2half(0.f);
        a_lo[b2i + q] = __float2half(0.f);
      }
    }
  }
  __syncthreads();

  wmma::fragment<wmma::accumulator, 16, 16, 16, float> acc[2][2];
  FILL_ACCS();
#pragma unroll
  for (int k = 0; k < 64; k += 16)  // stage 1a (h part)
    MMA_SPLIT_STEP(a_hi + wr * LDU + k, a_lo + wr * LDU + k, LDU,
                   wh + k * LDA + wc, wl + k * LDA + wc);
  __syncthreads();

  for (int i = tid; i < 4096; i += 256) {  // W1 rows [64,128)
    int k = i >> 6, c = i & 63;
    split2(__ldg(W1 + 4096 + i), wh[k * LDA + c], wl[k * LDA + c]);
  }
  __syncthreads();

#pragma unroll
  for (int k = 64; k < 128; k += 16)  // stage 1b (agg part)
    MMA_SPLIT_STEP(a_hi + wr * LDU + k, a_lo + wr * LDU + k, LDU,
                   wh + (k - 64) * LDA + wc, wl + (k - 64) * LDA + wc);
  __syncthreads();

  // pass A store + load W2
  STORE_ACCS(0);
  for (int i = tid; i < 4096; i += 256) {
    int k = i >> 6, c = i & 63;
    split2(__ldg(W2 + i), wh[k * LDA + c], wl[k * LDA + c]);
  }
  __syncthreads();
  {  // t rows [0,64) -> A region cols [0,64)
    int r = tid >> 2, c0 = (tid & 3) * 16;
#pragma unroll
    for (int q = 0; q < 16; q++) {
      int c = c0 + q;
      float t = fmaxf(fs[r * LDA + c] + __ldg(B1 + c), 0.f);
      split2(t, a_hi[r * LDU + c], a_lo[r * LDU + c]);
    }
  }
  __syncthreads();
  STORE_ACCS(64);
  __syncthreads();
  {  // t rows [64,128)
    int r = tid >> 2, c0 = (tid & 3) * 16;
#pragma unroll
    for (int q = 0; q < 16; q++) {
      int c = c0 + q;
      float t = fmaxf(fs[r * LDA + c] + __ldg(B1 + c), 0.f);
      split2(t, a_hi[(64 + r) * LDU + c], a_lo[(64 + r) * LDU + c]);
    }
  }
  __syncthreads();

  FILL_ACCS();
#pragma unroll
  for (int k = 0; k < 64; k += 16)  // stage 2
    MMA_SPLIT_STEP(a_hi + wr * LDU + k, a_lo + wr * LDU + k, LDU,
                   wh + k * LDA + wc, wl + k * LDA + wc);
  __syncthreads();

  STORE_ACCS(0);
  __syncthreads();
  {  // epilogue rows [0,64): bn + residual (fresh fp32 h from global)
    int r = tid >> 2, c0 = (tid & 3) * 16;
    int grow = rb + r;
    if (grow < N) {
      float* hp = (float*)g_h4 + (size_t)grow * 64 + c0;
#pragma unroll
      for (int q = 0; q < 4; q++) {
        float4 hold = ((float4*)hp)[q];
        float4 o;
        o.x = fmaxf(fmaf(fs[r * LDA + c0 + q * 4 + 0] + b2s[c0 + q * 4 + 0],
                         scs[c0 + q * 4 + 0], shs[c0 + q * 4 + 0]) + hold.x, 0.f);
        o.y = fmaxf(fmaf(fs[r * LDA + c0 + q * 4 + 1] + b2s[c0 + q * 4 + 1],
                         scs[c0 + q * 4 + 1], shs[c0 + q * 4 + 1]) + hold.y, 0.f);
        o.z = fmaxf(fmaf(fs[r * LDA + c0 + q * 4 + 2] + b2s[c0 + q * 4 + 2],
                         scs[c0 + q * 4 + 2], shs[c0 + q * 4 + 2]) + hold.z, 0.f);
        o.w = fmaxf(fmaf(fs[r * LDA + c0 + q * 4 + 3] + b2s[c0 + q * 4 + 3],
                         scs[c0 + q * 4 + 3], shs[c0 + q * 4 + 3]) + hold.w, 0.f);
        ((float4*)hp)[q] = o;
      }
    }
  }
  __syncthreads();
  STORE_ACCS(64);
  __syncthreads();
  {  // epilogue rows [64,128)
    int r = tid >> 2, c0 = (tid & 3) * 16;
    int grow = rb + 64 + r;
    if (grow < N) {
      float* hp = (float*)g_h4 + (size_t)grow * 64 + c0;
#pragma unroll
      for (int q = 0; q < 4; q++) {
        float4 hold = ((float4*)hp)[q];
        float4 o;
        o.x = fmaxf(fmaf(fs[r * LDA + c0 + q * 4 + 0] + b2s[c0 + q * 4 + 0],
                         scs[c0 + q * 4 + 0], shs[c0 + q * 4 + 0]) + hold.x, 0.f);
        o.y = fmaxf(fmaf(fs[r * LDA + c0 + q * 4 + 1] + b2s[c0 + q * 4 + 1],
                         scs[c0 + q * 4 + 1], shs[c0 + q * 4 + 1]) + hold.y, 0.f);
        o.z = fmaxf(fmaf(fs[r * LDA + c0 + q * 4 + 2] + b2s[c0 + q * 4 + 2],
                         scs[c0 + q * 4 + 2], shs[c0 + q * 4 + 2]) + hold.z, 0.f);
        o.w = fmaxf(fmaf(fs[r * LDA + c0 + q * 4 + 3] + b2s[c0 + q * 4 + 3],
                         scs[c0 + q * 4 + 3], shs[c0 + q * 4 + 3]) + hold.w, 0.f);
        ((float4*)hp)[q] = o;
      }
    }
  }
}

// ---------------------------------------------------------------------------
// out = relu(h[:NQ] @ out_w1 + b1) @ out_w2 + b2   (warp per node)
// ---------------------------------------------------------------------------
__global__ void __launch_bounds__(256) out_kernel(
    const float* __restrict__ w1, const float* __restrict__ b1,
    const float* __restrict__ w2, const float* __restrict__ b2,
    float* __restrict__ out, int NQ) {
  int warp = (blockIdx.x * blockDim.x + threadIdx.x) >> 5;
  int lane = threadIdx.x & 31;
  if (warp >= NQ) return;
  const float* h = (const float*)g_h4;
  float2 hv = ((const float2*)(h + (size_t)warp * 64))[lane];
  float acc = __ldg(b1 + lane);
#pragma unroll
  for (int kk = 0; kk < 32; kk++) {
    float hx = __shfl_sync(0xffffffffu, hv.x, kk);
    float hy = __shfl_sync(0xffffffffu, hv.y, kk);
    acc = fmaf(hx, __ldg(w1 + (2 * kk) * 32 + lane), acc);
    acc = fmaf(hy, __ldg(w1 + (2 * kk + 1) * 32 + lane), acc);
  }
  float v = fmaxf(acc, 0.f) * __ldg(w2 + lane);
#pragma unroll
  for (int o = 16; o; o >>= 1) v += __shfl_down_sync(0xffffffffu, v, o);
  if (lane == 0) out[warp] = v + __ldg(b2);
}

// ---------------------------------------------------------------------------
extern "C" void kernel_launch(void* const* d_in, const int* in_sizes, int n_in,
                              void* d_out, int out_size) {
  int off = (n_in >= 21) ? 1 : 0;
  const float* x      = (const float*)d_in[0];
  const int*   ei     = (const int*)d_in[1];
  const float* w_in   = (const float*)d_in[2 + off];
  const float* b_in   = (const float*)d_in[3 + off];
  const float* msg_w1 = (const float*)d_in[4 + off];
  const float* msg_b1 = (const float*)d_in[5 + off];
  const float* msg_w2 = (const float*)d_in[6 + off];
  const float* msg_b2 = (const float*)d_in[7 + off];
  const float* upd_w1 = (const float*)d_in[8 + off];
  const float* upd_b1 = (const float*)d_in[9 + off];
  const float* upd_w2 = (const float*)d_in[10 + off];
  const float* upd_b2 = (const float*)d_in[11 + off];
  const float* bn_g   = (const float*)d_in[12 + off];
  const float* bn_b   = (const float*)d_in[13 + off];
  const float* bn_m   = (const float*)d_in[14 + off];
  const float* bn_v   = (const float*)d_in[15 + off];
  const float* out_w1 = (const float*)d_in[16 + off];
  const float* out_b1 = (const float*)d_in[17 + off];
  const float* out_w2 = (const float*)d_in[18 + off];
  const float* out_b2 = (const float*)d_in[19 + off];

  int N = in_sizes[0] / 3;
  int E = in_sizes[1] / 2;
  int L = in_sizes[4 + off] / (64 * 64);
  int NQ = out_size;

  const int MSG_SMEM =
      (2 * 128 * LDA + 2 * 64 * LDA) * 2 + 64 * LDA * 4;  // 73,728 B
  const int UPD_SMEM =
      (2 * 128 * LDU + 2 * 64 * LDA) * 2 + 64 * LDA * 4;  // 106,496 B
  cudaFuncSetAttribute(msg_kernel, cudaFuncAttributeMaxDynamicSharedMemorySize,
                       MSG_SMEM);
  cudaFuncSetAttribute(upd_kernel, cudaFuncAttributeMaxDynamicSharedMemorySize,
                       UPD_SMEM);

  int gb = (N + NROWS - 1) / NROWS;
  int nb_scan = (N + 1023) / 1024;

  // msg_kernel kept as 4th launch so ncu (-s 5 -c 1) profiles it again (A/B).
  input_kernel<<<(N * 64 + 255) / 256, 256>>>(x, w_in, b_in, N);
  zero_counts_kernel<<<(N + 255) / 256, 256>>>(N);
  hist_kernel<<<(E + 255) / 256, 256>>>(ei, E);
  msg_kernel<<<gb, 256, MSG_SMEM>>>(msg_w1, msg_b1, msg_w2, msg_b2, N);
  scan1_kernel<<<nb_scan, 1024>>>(N);
  scan2_kernel<<<1, 128>>>(nb_scan);
  scan3_kernel<<<(N + 255) / 256, 256>>>(N);
  fill_kernel<<<(E + 255) / 256, 256>>>(ei, E);

  for (int l = 0; l < L; l++) {
    if (l > 0)
      msg_kernel<<<gb, 256, MSG_SMEM>>>(msg_w1 + l * 4096, msg_b1 + l * 64,
                                        msg_w2 + l * 4096, msg_b2 + l * 64, N);
    gather_kernel<<<(N * 32 + 255) / 256, 256>>>(N);
    upd_kernel<<<gb, 256, UPD_SMEM>>>(
        upd_w1 + l * 8192, upd_b1 + l * 64, upd_w2 + l * 4096, upd_b2 + l * 64,
        bn_g + l * 64, bn_b + l * 64, bn_m + l * 64, bn_v + l * 64, N);
  }

  out_kernel<<<(NQ * 32 + 255) / 256, 256>>>(out_w1, out_b1, out_w2, out_b2,
                                             (float*)d_out, NQ);
}

// round 8
// speedup vs baseline: 1.4092x; 1.3898x over previous
#include <cuda_runtime.h>
#include <cuda_fp16.h>
#include <mma.h>

using namespace nvcuda;

#define MAXN 100000
#define MAXE 1600000
#define MAXL 8
#define TROWS 64

// Persistent scratch (no allocations allowed). float4 arrays for 16B align.
__device__ float4 g_hh4[MAXN * 8];   // h hi (half, N x 64)
__device__ float4 g_hl4[MAXN * 8];   // h lo
__device__ float4 g_ah4[MAXN * 8];   // agg hi
__device__ float4 g_al4[MAXN * 8];   // agg lo
__device__ float4 g_Mh4[MAXN * 8];   // M (fp16, N x 64)
__device__ float4 g_wh4[MAXL * 2560];  // all weights hi (20480 half / layer)
__device__ float4 g_wl4[MAXL * 2560];  // all weights lo
// CSR
__device__ int g_counts[MAXN];
__device__ int g_rowstart[MAXN];
__device__ int g_rowend[MAXN];
__device__ int g_csrsrc[MAXE];
__device__ int g_blocksum[128];

__device__ __forceinline__ void split2(float x, __half& hi, __half& lo) {
  hi = __float2half_rn(x);
  lo = __float2half_rn(x - __half2float(hi));
}

// ---------------------------------------------------------------------------
// Pre-split all layer weights into persistent hi/lo half arrays.
// Per-layer layout (halves): [0,4096) msgW1, [4096,8192) msgW2,
// [8192,16384) updW1, [16384,20480) updW2.
// ---------------------------------------------------------------------------
__global__ void __launch_bounds__(256) wprep_kernel(
    const float* __restrict__ mw1, const float* __restrict__ mw2,
    const float* __restrict__ uw1, const float* __restrict__ uw2, int L) {
  int i = blockIdx.x * blockDim.x + threadIdx.x;
  int total = L * 20480;
  if (i >= total) return;
  int l = i / 20480, off = i % 20480;
  float v;
  if (off < 4096) v = __ldg(mw1 + l * 4096 + off);
  else if (off < 8192) v = __ldg(mw2 + l * 4096 + off - 4096);
  else if (off < 16384) v = __ldg(uw1 + l * 8192 + off - 8192);
  else v = __ldg(uw2 + l * 4096 + off - 16384);
  __half hi, lo;
  split2(v, hi, lo);
  ((__half*)g_wh4)[i] = hi;
  ((__half*)g_wl4)[i] = lo;
}

// ---------------------------------------------------------------------------
// h = relu(x @ w_in + b_in), stored split
// ---------------------------------------------------------------------------
__global__ void __launch_bounds__(256) input_kernel(
    const float* __restrict__ x, const float* __restrict__ w_in,
    const float* __restrict__ b_in, int N) {
  int i = blockIdx.x * blockDim.x + threadIdx.x;
  if (i >= N * 64) return;
  int node = i >> 6, c = i & 63;
  float acc = __ldg(b_in + c);
  acc = fmaf(__ldg(x + node * 3 + 0), __ldg(w_in + c), acc);
  acc = fmaf(__ldg(x + node * 3 + 1), __ldg(w_in + 64 + c), acc);
  acc = fmaf(__ldg(x + node * 3 + 2), __ldg(w_in + 128 + c), acc);
  float h = fmaxf(acc, 0.f);
  __half hi, lo;
  split2(h, hi, lo);
  ((__half*)g_hh4)[i] = hi;
  ((__half*)g_hl4)[i] = lo;
}

// ---------------------------------------------------------------------------
// CSR build
// ---------------------------------------------------------------------------
__global__ void __launch_bounds__(256) zero_counts_kernel(int N) {
  int i = blockIdx.x * blockDim.x + threadIdx.x;
  if (i < N) g_counts[i] = 0;
}

__global__ void __launch_bounds__(256) hist_kernel(const int* __restrict__ ei,
                                                   int E) {
  int e = blockIdx.x * blockDim.x + threadIdx.x;
  if (e < E) atomicAdd(&g_counts[__ldg(ei + E + e)], 1);
}

__global__ void __launch_bounds__(1024) scan1_kernel(int N) {
  __shared__ int sh[1024];
  int t = threadIdx.x;
  int idx = blockIdx.x * 1024 + t;
  int v = (idx < N) ? g_counts[idx] : 0;
  sh[t] = v;
  __syncthreads();
#pragma unroll
  for (int off = 1; off < 1024; off <<= 1) {
    int x = (t >= off) ? sh[t - off] : 0;
    __syncthreads();
    sh[t] += x;
    __syncthreads();
  }
  if (idx < N) g_rowstart[idx] = sh[t] - v;
  if (t == 1023) g_blocksum[blockIdx.x] = sh[1023];
}

__global__ void __launch_bounds__(128) scan2_kernel(int nb) {
  __shared__ int sh[128];
  int t = threadIdx.x;
  int v = (t < nb) ? g_blocksum[t] : 0;
  sh[t] = v;
  __syncthreads();
#pragma unroll
  for (int off = 1; off < 128; off <<= 1) {
    int x = (t >= off) ? sh[t - off] : 0;
    __syncthreads();
    sh[t] += x;
    __syncthreads();
  }
  if (t < nb) g_blocksum[t] = sh[t] - v;
}

__global__ void __launch_bounds__(256) scan3_kernel(int N) {
  int i = blockIdx.x * blockDim.x + threadIdx.x;
  if (i < N) {
    int v = g_rowstart[i] + g_blocksum[i >> 10];
    g_rowstart[i] = v;
    g_rowend[i] = v;
  }
}

__global__ void __launch_bounds__(256) fill_kernel(const int* __restrict__ ei,
                                                   int E) {
  int e = blockIdx.x * blockDim.x + threadIdx.x;
  if (e < E) {
    int d = __ldg(ei + E + e);
    int pos = atomicAdd(&g_rowend[d], 1);
    g_csrsrc[pos] = __ldg(ei + e);
  }
}

// ---------------------------------------------------------------------------
// agg[i] = sum_{e: dst(e)=i} M[src(e)]; agg stored split (hi/lo half)
// ---------------------------------------------------------------------------
__global__ void __launch_bounds__(256) gather_kernel(int N) {
  int w = (blockIdx.x * blockDim.x + threadIdx.x) >> 5;
  int lane = threadIdx.x & 31;
  if (w >= N) return;
  int s = __ldg(&g_rowstart[w]);
  int e = __ldg(&g_rowend[w]);
  const __half2* M = (const __half2*)g_Mh4;
  float2 a0 = make_float2(0.f, 0.f), a1 = make_float2(0.f, 0.f);
  int j = s;
  for (; j + 2 <= e; j += 2) {
    int s0 = __ldg(&g_csrsrc[j]);
    int s1 = __ldg(&g_csrsrc[j + 1]);
    float2 v0 = __half22float2(__ldg(&M[(size_t)s0 * 32 + lane]));
    float2 v1 = __half22float2(__ldg(&M[(size_t)s1 * 32 + lane]));
    a0.x += v0.x; a0.y += v0.y;
    a1.x += v1.x; a1.y += v1.y;
  }
  if (j < e) {
    int s0 = __ldg(&g_csrsrc[j]);
    float2 v0 = __half22float2(__ldg(&M[(size_t)s0 * 32 + lane]));
    a0.x += v0.x; a0.y += v0.y;
  }
  float sx = a0.x + a1.x, sy = a0.y + a1.y;
  __half h0, l0, h1, l1;
  split2(sx, h0, l0);
  split2(sy, h1, l1);
  ((__half2*)g_ah4)[(size_t)w * 32 + lane] = __halves2half2(h0, h1);
  ((__half2*)g_al4)[(size_t)w * 32 + lane] = __halves2half2(l0, l1);
}

// 3-term split MMA: one 16-row A tile x two 16-col B frags.
#define MMA_STEP3(APH, APL, LDAX, BPH, BPL)                                  \
  {                                                                          \
    wmma::fragment<wmma::matrix_a, 16, 16, 16, __half, wmma::row_major> ah, \
        al;                                                                  \
    wmma::fragment<wmma::matrix_b, 16, 16, 16, __half, wmma::row_major>    \
        bh0, bh1, bl0, bl1;                                                  \
    wmma::load_matrix_sync(ah, (APH), (LDAX));                               \
    wmma::load_matrix_sync(al, (APL), (LDAX));                               \
    wmma::load_matrix_sync(bh0, (BPH), 72);                                  \
    wmma::load_matrix_sync(bh1, (BPH) + 16, 72);                             \
    wmma::load_matrix_sync(bl0, (BPL), 72);                                  \
    wmma::load_matrix_sync(bl1, (BPL) + 16, 72);                             \
    wmma::mma_sync(acc0, ah, bh0, acc0);                                     \
    wmma::mma_sync(acc0, al, bh0, acc0);                                     \
    wmma::mma_sync(acc0, ah, bl0, acc0);                                     \
    wmma::mma_sync(acc1, ah, bh1, acc1);                                     \
    wmma::mma_sync(acc1, al, bh1, acc1);                                     \
    wmma::mma_sync(acc1, ah, bl1, acc1);                                     \
  }

// ---------------------------------------------------------------------------
// msg: M = relu(h @ W1 + b1) @ W2 + b2.  64-row tile, 256 thr, 4 barriers.
// smem: a pair 64x72, W1 pair 64x72, W2 pair 64x72, fs 64x72 f32 = 73728 B.
// ---------------------------------------------------------------------------
__global__ void __launch_bounds__(256) msg_kernel(
    const __half* __restrict__ wh, const __half* __restrict__ wl,
    const float* __restrict__ B1, const float* __restrict__ B2, int N) {
  extern __shared__ char smc[];
  __half* a_hi = (__half*)smc;       // 64 x 72
  __half* a_lo = a_hi + 64 * 72;
  __half* w1h = a_lo + 64 * 72;      // 64 x 72
  __half* w1l = w1h + 64 * 72;
  __half* w2h = w1l + 64 * 72;
  __half* w2l = w2h + 64 * 72;
  float* fs = (float*)(w2l + 64 * 72);  // 64 x 72
  __shared__ float sb1[64], sb2[64];

  int tid = threadIdx.x;
  int rb = blockIdx.x * TROWS;

  // ---- stage (pure uint4 copies) ----
  for (int j = tid; j < 512; j += 256) {  // W1 hi
    int k = j >> 3, ch = j & 7;
    *(uint4*)((char*)w1h + k * 144 + ch * 16) = __ldg((const uint4*)wh + j);
  }
  for (int j = tid; j < 512; j += 256) {  // W1 lo
    int k = j >> 3, ch = j & 7;
    *(uint4*)((char*)w1l + k * 144 + ch * 16) = __ldg((const uint4*)wl + j);
  }
  for (int j = tid; j < 512; j += 256) {  // W2 hi
    int k = j >> 3, ch = j & 7;
    *(uint4*)((char*)w2h + k * 144 + ch * 16) =
        __ldg((const uint4*)(wh + 4096) + j);
  }
  for (int j = tid; j < 512; j += 256) {  // W2 lo
    int k = j >> 3, ch = j & 7;
    *(uint4*)((char*)w2l + k * 144 + ch * 16) =
        __ldg((const uint4*)(wl + 4096) + j);
  }
  for (int j = tid; j < 512; j += 256) {  // A hi
    int r = j >> 3, ch = j & 7;
    int grow = rb + r;
    uint4 v = make_uint4(0, 0, 0, 0);
    if (grow < N)
      v = __ldg((const uint4*)((const char*)g_hh4 + (size_t)grow * 128) + ch);
    *(uint4*)((char*)a_hi + r * 144 + ch * 16) = v;
  }
  for (int j = tid; j < 512; j += 256) {  // A lo
    int r = j >> 3, ch = j & 7;
    int grow = rb + r;
    uint4 v = make_uint4(0, 0, 0, 0);
    if (grow < N)
      v = __ldg((const uint4*)((const char*)g_hl4 + (size_t)grow * 128) + ch);
    *(uint4*)((char*)a_lo + r * 144 + ch * 16) = v;
  }
  if (tid < 64) {
    sb1[tid] = __ldg(B1 + tid);
    sb2[tid] = __ldg(B2 + tid);
  }
  __syncthreads();

  int wid = tid >> 5;
  int wr = (wid & 3) * 16, wc = (wid >> 2) * 32;

  wmma::fragment<wmma::accumulator, 16, 16, 16, float> acc0, acc1;
  wmma::fill_fragment(acc0, 0.f);
  wmma::fill_fragment(acc1, 0.f);
#pragma unroll
  for (int k = 0; k < 64; k += 16)
    MMA_STEP3(a_hi + wr * 72 + k, a_lo + wr * 72 + k, 72, w1h + k * 72 + wc,
              w1l + k * 72 + wc);
  wmma::store_matrix_sync(fs + wr * 72 + wc, acc0, 72, wmma::mem_row_major);
  wmma::store_matrix_sync(fs + wr * 72 + wc + 16, acc1, 72,
                          wmma::mem_row_major);
  __syncthreads();

  // t = relu(fs + b1) -> a buffers (split)
  {
    int r = tid >> 2, c0 = (tid & 3) << 4;
#pragma unroll
    for (int q = 0; q < 4; q++) {
      int c = c0 + q * 4;
      float4 v = *(const float4*)(fs + r * 72 + c);
      float t0 = fmaxf(v.x + sb1[c + 0], 0.f);
      float t1 = fmaxf(v.y + sb1[c + 1], 0.f);
      float t2 = fmaxf(v.z + sb1[c + 2], 0.f);
      float t3 = fmaxf(v.w + sb1[c + 3], 0.f);
      __half h0, l0, h1, l1, h2, l2, h3, l3;
      split2(t0, h0, l0); split2(t1, h1, l1);
      split2(t2, h2, l2); split2(t3, h3, l3);
      *(__half2*)(a_hi + r * 72 + c) = __halves2half2(h0, h1);
      *(__half2*)(a_hi + r * 72 + c + 2) = __halves2half2(h2, h3);
      *(__half2*)(a_lo + r * 72 + c) = __halves2half2(l0, l1);
      *(__half2*)(a_lo + r * 72 + c + 2) = __halves2half2(l2, l3);
    }
  }
  __syncthreads();

  wmma::fill_fragment(acc0, 0.f);
  wmma::fill_fragment(acc1, 0.f);
#pragma unroll
  for (int k = 0; k < 64; k += 16)
    MMA_STEP3(a_hi + wr * 72 + k, a_lo + wr * 72 + k, 72, w2h + k * 72 + wc,
              w2l + k * 72 + wc);
  wmma::store_matrix_sync(fs + wr * 72 + wc, acc0, 72, wmma::mem_row_major);
  wmma::store_matrix_sync(fs + wr * 72 + wc + 16, acc1, 72,
                          wmma::mem_row_major);
  __syncthreads();

  // M = fs + b2 (fp16, straight to global)
  {
    int r = tid >> 2, c0 = (tid & 3) << 4;
    int grow = rb + r;
    if (grow < N) {
      __half* mp = (__half*)g_Mh4 + (size_t)grow * 64 + c0;
#pragma unroll
      for (int q = 0; q < 4; q++) {
        int c = c0 + q * 4;
        float4 v = *(const float4*)(fs + r * 72 + c);
        *(__half2*)(mp + q * 4) =
            __floats2half2_rn(v.x + sb2[c + 0], v.y + sb2[c + 1]);
        *(__half2*)(mp + q * 4 + 2) =
            __floats2half2_rn(v.z + sb2[c + 2], v.w + sb2[c + 3]);
      }
    }
  }
}

// ---------------------------------------------------------------------------
// upd: hn = relu([h,agg] @ W1 + b1) @ W2 + b2 ; bn ; h = relu(hn + h)
// 64-row tile. A = 64 x 136 (k<64: h, k>=64: agg, later t). 4 barriers.
// smem: A pair 34816 + W1 pair 36864 + W2 pair 18432 + fs 18432 = 108544 B.
// ---------------------------------------------------------------------------
__global__ void __launch_bounds__(256) upd_kernel(
    const __half* __restrict__ wh, const __half* __restrict__ wl,
    const float* __restrict__ B1, const float* __restrict__ B2,
    const float* __restrict__ Gm, const float* __restrict__ Bt,
    const float* __restrict__ Mn, const float* __restrict__ Vr, int N) {
  extern __shared__ char smc[];
  __half* a_hi = (__half*)smc;        // 64 x 136
  __half* a_lo = a_hi + 64 * 136;
  __half* w1h = a_lo + 64 * 136;      // 128 x 72
  __half* w1l = w1h + 128 * 72;
  __half* w2h = w1l + 128 * 72;       // 64 x 72
  __half* w2l = w2h + 64 * 72;
  float* fs = (float*)(w2l + 64 * 72);  // 64 x 72
  __shared__ float sb1[64], b2s[64], scs[64], shs[64];

  int tid = threadIdx.x;
  int rb = blockIdx.x * TROWS;

  // ---- stage ----
  for (int j = tid; j < 1024; j += 256) {  // W1 hi (128 k-rows)
    int k = j >> 3, ch = j & 7;
    *(uint4*)((char*)w1h + k * 144 + ch * 16) = __ldg((const uint4*)wh + j);
  }
  for (int j = tid; j < 1024; j += 256) {  // W1 lo
    int k = j >> 3, ch = j & 7;
    *(uint4*)((char*)w1l + k * 144 + ch * 16) = __ldg((const uint4*)wl + j);
  }
  for (int j = tid; j < 512; j += 256) {  // W2 hi
    int k = j >> 3, ch = j & 7;
    *(uint4*)((char*)w2h + k * 144 + ch * 16) =
        __ldg((const uint4*)(wh + 8192) + j);
  }
  for (int j = tid; j < 512; j += 256) {  // W2 lo
    int k = j >> 3, ch = j & 7;
    *(uint4*)((char*)w2l + k * 144 + ch * 16) =
        __ldg((const uint4*)(wl + 8192) + j);
  }
  for (int j = tid; j < 512; j += 256) {  // A hi: h -> k cols [0,64)
    int r = j >> 3, ch = j & 7;
    int grow = rb + r;
    uint4 v = make_uint4(0, 0, 0, 0);
    if (grow < N)
      v = __ldg((const uint4*)((const char*)g_hh4 + (size_t)grow * 128) + ch);
    *(uint4*)((char*)a_hi + r * 272 + ch * 16) = v;
  }
  for (int j = tid; j < 512; j += 256) {  // A hi: agg -> k cols [64,128)
    int r = j >> 3, ch = j & 7;
    int grow = rb + r;
    uint4 v = make_uint4(0, 0, 0, 0);
    if (grow < N)
      v = __ldg((const uint4*)((const char*)g_ah4 + (size_t)grow * 128) + ch);
    *(uint4*)((char*)a_hi + r * 272 + 128 + ch * 16) = v;
  }
  for (int j = tid; j < 512; j += 256) {  // A lo: h
    int r = j >> 3, ch = j & 7;
    int grow = rb + r;
    uint4 v = make_uint4(0, 0, 0, 0);
    if (grow < N)
      v = __ldg((const uint4*)((const char*)g_hl4 + (size_t)grow * 128) + ch);
    *(uint4*)((char*)a_lo + r * 272 + ch * 16) = v;
  }
  for (int j = tid; j < 512; j += 256) {  // A lo: agg
    int r = j >> 3, ch = j & 7;
    int grow = rb + r;
    uint4 v = make_uint4(0, 0, 0, 0);
    if (grow < N)
      v = __ldg((const uint4*)((const char*)g_al4 + (size_t)grow * 128) + ch);
    *(uint4*)((char*)a_lo + r * 272 + 128 + ch * 16) = v;
  }
  if (tid < 64) {
    float s = __ldg(Gm + tid) * rsqrtf(__ldg(Vr + tid) + 1e-5f);
    scs[tid] = s;
    shs[tid] = __ldg(Bt + tid) - __ldg(Mn + tid) * s;
    sb1[tid] = __ldg(B1 + tid);
    b2s[tid] = __ldg(B2 + tid);
  }
  __syncthreads();

  int wid = tid >> 5;
  int wr = (wid & 3) * 16, wc = (wid >> 2) * 32;

  wmma::fragment<wmma::accumulator, 16, 16, 16, float> acc0, acc1;
  wmma::fill_fragment(acc0, 0.f);
  wmma::fill_fragment(acc1, 0.f);
#pragma unroll
  for (int k = 0; k < 128; k += 16)
    MMA_STEP3(a_hi + wr * 136 + k, a_lo + wr * 136 + k, 136,
              w1h + k * 72 + wc, w1l + k * 72 + wc);
  wmma::store_matrix_sync(fs + wr * 72 + wc, acc0, 72, wmma::mem_row_major);
  wmma::store_matrix_sync(fs + wr * 72 + wc + 16, acc1, 72,
                          wmma::mem_row_major);
  __syncthreads();

  // t = relu(fs + b1) -> A k cols [64,128) (agg region, no longer needed)
  {
    int r = tid >> 2, c0 = (tid & 3) << 4;
#pragma unroll
    for (int q = 0; q < 4; q++) {
      int c = c0 + q * 4;
      float4 v = *(const float4*)(fs + r * 72 + c);
      float t0 = fmaxf(v.x + sb1[c + 0], 0.f);
      float t1 = fmaxf(v.y + sb1[c + 1], 0.f);
      float t2 = fmaxf(v.z + sb1[c + 2], 0.f);
      float t3 = fmaxf(v.w + sb1[c + 3], 0.f);
      __half h0, l0, h1, l1, h2, l2, h3, l3;
      split2(t0, h0, l0); split2(t1, h1, l1);
      split2(t2, h2, l2); split2(t3, h3, l3);
      *(__half2*)(a_hi + r * 136 + 64 + c) = __halves2half2(h0, h1);
      *(__half2*)(a_hi + r * 136 + 64 + c + 2) = __halves2half2(h2, h3);
      *(__half2*)(a_lo + r * 136 + 64 + c) = __halves2half2(l0, l1);
      *(__half2*)(a_lo + r * 136 + 64 + c + 2) = __halves2half2(l2, l3);
    }
  }
  __syncthreads();

  wmma::fill_fragment(acc0, 0.f);
  wmma::fill_fragment(acc1, 0.f);
#pragma unroll
  for (int k = 0; k < 64; k += 16)
    MMA_STEP3(a_hi + wr * 136 + 64 + k, a_lo + wr * 136 + 64 + k, 136,
              w2h + k * 72 + wc, w2l + k * 72 + wc);
  wmma::store_matrix_sync(fs + wr * 72 + wc, acc0, 72, wmma::mem_row_major);
  wmma::store_matrix_sync(fs + wr * 72 + wc + 16, acc1, 72,
                          wmma::mem_row_major);
  __syncthreads();

  // h = relu(bn(fs + b2) + h_old), h_old = hi+lo from global; write split
  {
    int r = tid >> 2, c0 = (tid & 3) << 4;
    int grow = rb + r;
    if (grow < N) {
      const __half2* hh2 = (const __half2*)((const char*)g_hh4 +
                                            (size_t)grow * 128 + c0 * 2);
      const __half2* hl2 = (const __half2*)((const char*)g_hl4 +
                                            (size_t)grow * 128 + c0 * 2);
      __half2 oh[8], ol[8];
#pragma unroll
      for (int q = 0; q < 8; q++) {
        float2 hi2 = __half22float2(hh2[q]);
        float2 lo2 = __half22float2(hl2[q]);
        int c = c0 + 2 * q;
        float v0 = fs[r * 72 + c] + b2s[c];
        float v1 = fs[r * 72 + c + 1] + b2s[c + 1];
        float o0 = fmaxf(fmaf(v0, scs[c], shs[c]) + hi2.x + lo2.x, 0.f);
        float o1 = fmaxf(fmaf(v1, scs[c + 1], shs[c + 1]) + hi2.y + lo2.y,
                         0.f);
        __half h0, l0, h1, l1;
        split2(o0, h0, l0);
        split2(o1, h1, l1);
        oh[q] = __halves2half2(h0, h1);
        ol[q] = __halves2half2(l0, l1);
      }
      __half2* dh = (__half2*)((char*)g_hh4 + (size_t)grow * 128 + c0 * 2);
      __half2* dl = (__half2*)((char*)g_hl4 + (size_t)grow * 128 + c0 * 2);
#pragma unroll
      for (int q = 0; q < 8; q++) {
        dh[q] = oh[q];
        dl[q] = ol[q];
      }
    }
  }
}

// ---------------------------------------------------------------------------
// out = relu(h[:NQ] @ out_w1 + b1) @ out_w2 + b2   (warp per node)
// ---------------------------------------------------------------------------
__global__ void __launch_bounds__(256) out_kernel(
    const float* __restrict__ w1, const float* __restrict__ b1,
    const float* __restrict__ w2, const float* __restrict__ b2,
    float* __restrict__ out, int NQ) {
  int warp = (blockIdx.x * blockDim.x + threadIdx.x) >> 5;
  int lane = threadIdx.x & 31;
  if (warp >= NQ) return;
  float2 hh = __half22float2(((const __half2*)g_hh4)[(size_t)warp * 32 + lane]);
  float2 hl = __half22float2(((const __half2*)g_hl4)[(size_t)warp * 32 + lane]);
  float2 hv = make_float2(hh.x + hl.x, hh.y + hl.y);
  float acc = __ldg(b1 + lane);
#pragma unroll
  for (int kk = 0; kk < 32; kk++) {
    float hx = __shfl_sync(0xffffffffu, hv.x, kk);
    float hy = __shfl_sync(0xffffffffu, hv.y, kk);
    acc = fmaf(hx, __ldg(w1 + (2 * kk) * 32 + lane), acc);
    acc = fmaf(hy, __ldg(w1 + (2 * kk + 1) * 32 + lane), acc);
  }
  float v = fmaxf(acc, 0.f) * __ldg(w2 + lane);
#pragma unroll
  for (int o = 16; o; o >>= 1) v += __shfl_down_sync(0xffffffffu, v, o);
  if (lane == 0) out[warp] = v + __ldg(b2);
}

// ---------------------------------------------------------------------------
extern "C" void kernel_launch(void* const* d_in, const int* in_sizes, int n_in,
                              void* d_out, int out_size) {
  int off = (n_in >= 21) ? 1 : 0;
  const float* x      = (const float*)d_in[0];
  const int*   ei     = (const int*)d_in[1];
  const float* w_in   = (const float*)d_in[2 + off];
  const float* b_in   = (const float*)d_in[3 + off];
  const float* msg_w1 = (const float*)d_in[4 + off];
  const float* msg_b1 = (const float*)d_in[5 + off];
  const float* msg_w2 = (const float*)d_in[6 + off];
  const float* msg_b2 = (const float*)d_in[7 + off];
  const float* upd_w1 = (const float*)d_in[8 + off];
  const float* upd_b1 = (const float*)d_in[9 + off];
  const float* upd_w2 = (const float*)d_in[10 + off];
  const float* upd_b2 = (const float*)d_in[11 + off];
  const float* bn_g   = (const float*)d_in[12 + off];
  const float* bn_b   = (const float*)d_in[13 + off];
  const float* bn_m   = (const float*)d_in[14 + off];
  const float* bn_v   = (const float*)d_in[15 + off];
  const float* out_w1 = (const float*)d_in[16 + off];
  const float* out_b1 = (const float*)d_in[17 + off];
  const float* out_w2 = (const float*)d_in[18 + off];
  const float* out_b2 = (const float*)d_in[19 + off];

  int N = in_sizes[0] / 3;
  int E = in_sizes[1] / 2;
  int L = in_sizes[4 + off] / (64 * 64);
  int NQ = out_size;

  const int MSG_SMEM = 6 * 64 * 72 * 2 + 64 * 72 * 4;            // 73,728 B
  const int UPD_SMEM =
      (2 * 64 * 136 + 2 * 128 * 72 + 2 * 64 * 72) * 2 + 64 * 72 * 4;  // 108,544
  cudaFuncSetAttribute(msg_kernel, cudaFuncAttributeMaxDynamicSharedMemorySize,
                       MSG_SMEM);
  cudaFuncSetAttribute(upd_kernel, cudaFuncAttributeMaxDynamicSharedMemorySize,
                       UPD_SMEM);

  int gb = (N + TROWS - 1) / TROWS;
  int nb_scan = (N + 1023) / 1024;

  const __half* wh = (const __half*)g_wh4;
  const __half* wl = (const __half*)g_wl4;
  // device-symbol addresses differ host-side; use the device pointers via
  // kernel args computed from the symbol in device code instead:
  // simplest: pass layer offsets and index inside kernels via the globals.
  // Here we get the device address of the symbol:
  void* whp = nullptr;
  void* wlp = nullptr;
  cudaGetSymbolAddress(&whp, g_wh4);
  cudaGetSymbolAddress(&wlp, g_wl4);
  wh = (const __half*)whp;
  wl = (const __half*)wlp;

  // Order: wprep(1), input(2), zero(3), msg0(4) <- profiled, hist(5), ...
  wprep_kernel<<<(L * 20480 + 255) / 256, 256>>>(msg_w1, msg_w2, upd_w1,
                                                 upd_w2, L);
  input_kernel<<<(N * 64 + 255) / 256, 256>>>(x, w_in, b_in, N);
  zero_counts_kernel<<<(N + 255) / 256, 256>>>(N);
  msg_kernel<<<gb, 256, MSG_SMEM>>>(wh, wl, msg_b1, msg_b2, N);
  hist_kernel<<<(E + 255) / 256, 256>>>(ei, E);
  scan1_kernel<<<nb_scan, 1024>>>(N);
  scan2_kernel<<<1, 128>>>(nb_scan);
  scan3_kernel<<<(N + 255) / 256, 256>>>(N);
  fill_kernel<<<(E + 255) / 256, 256>>>(ei, E);

  for (int l = 0; l < L; l++) {
    if (l > 0)
      msg_kernel<<<gb, 256, MSG_SMEM>>>(wh + l * 20480, wl + l * 20480,
                                        msg_b1 + l * 64, msg_b2 + l * 64, N);
    gather_kernel<<<(N * 32 + 255) / 256, 256>>>(N);
    upd_kernel<<<gb, 256, UPD_SMEM>>>(
        wh + l * 20480 + 8192, wl + l * 20480 + 8192, upd_b1 + l * 64,
        upd_b2 + l * 64, bn_g + l * 64, bn_b + l * 64, bn_m + l * 64,
        bn_v + l * 64, N);
  }

  out_kernel<<<(NQ * 32 + 255) / 256, 256>>>(out_w1, out_b1, out_w2, out_b2,
                                             (float*)d_out, NQ);
}

// round 9
// speedup vs baseline: 1.6100x; 1.1425x over previous
#include <cuda_runtime.h>
#include <cuda_fp16.h>
#include <mma.h>

using namespace nvcuda;

#define MAXN 100000
#define MAXE 1600000
#define MAXL 8
#define TROWS 64

// Persistent scratch (no allocations allowed). float4 arrays for 16B align.
__device__ float4 g_hh4[MAXN * 8];   // h hi (half, N x 64)
__device__ float4 g_hl4[MAXN * 8];   // h lo
__device__ float4 g_ah4[MAXN * 8];   // agg hi
__device__ float4 g_al4[MAXN * 8];   // agg lo
__device__ float4 g_Mh4[MAXN * 8];   // M (fp16, N x 64)
__device__ float4 g_wh4[MAXL * 2560];  // all weights hi (20480 half / layer)
__device__ float4 g_wl4[MAXL * 2560];  // all weights lo
// CSR
__device__ int g_counts[MAXN];
__device__ int g_rowstart[MAXN];
__device__ int g_rowend[MAXN];
__device__ int g_csrsrc[MAXE];
__device__ int g_blocksum[128];

__device__ __forceinline__ void split2(float x, __half& hi, __half& lo) {
  hi = __float2half_rn(x);
  lo = __float2half_rn(x - __half2float(hi));
}

// ---------------------------------------------------------------------------
// Pre-split all layer weights into persistent hi/lo half arrays.
// Per-layer halves: [0,4096) msgW1, [4096,8192) msgW2, [8192,16384) updW1,
// [16384,20480) updW2.
// ---------------------------------------------------------------------------
__global__ void __launch_bounds__(256) wprep_kernel(
    const float* __restrict__ mw1, const float* __restrict__ mw2,
    const float* __restrict__ uw1, const float* __restrict__ uw2, int L) {
  int i = blockIdx.x * blockDim.x + threadIdx.x;
  int total = L * 20480;
  if (i >= total) return;
  int l = i / 20480, off = i % 20480;
  float v;
  if (off < 4096) v = __ldg(mw1 + l * 4096 + off);
  else if (off < 8192) v = __ldg(mw2 + l * 4096 + off - 4096);
  else if (off < 16384) v = __ldg(uw1 + l * 8192 + off - 8192);
  else v = __ldg(uw2 + l * 4096 + off - 16384);
  __half hi, lo;
  split2(v, hi, lo);
  ((__half*)g_wh4)[i] = hi;
  ((__half*)g_wl4)[i] = lo;
}

// ---------------------------------------------------------------------------
// h = relu(x @ w_in + b_in), stored split
// ---------------------------------------------------------------------------
__global__ void __launch_bounds__(256) input_kernel(
    const float* __restrict__ x, const float* __restrict__ w_in,
    const float* __restrict__ b_in, int N) {
  int i = blockIdx.x * blockDim.x + threadIdx.x;
  if (i >= N * 64) return;
  int node = i >> 6, c = i & 63;
  float acc = __ldg(b_in + c);
  acc = fmaf(__ldg(x + node * 3 + 0), __ldg(w_in + c), acc);
  acc = fmaf(__ldg(x + node * 3 + 1), __ldg(w_in + 64 + c), acc);
  acc = fmaf(__ldg(x + node * 3 + 2), __ldg(w_in + 128 + c), acc);
  float h = fmaxf(acc, 0.f);
  __half hi, lo;
  split2(h, hi, lo);
  ((__half*)g_hh4)[i] = hi;
  ((__half*)g_hl4)[i] = lo;
}

// ---------------------------------------------------------------------------
// CSR build
// ---------------------------------------------------------------------------
__global__ void __launch_bounds__(256) zero_counts_kernel(int N) {
  int i = blockIdx.x * blockDim.x + threadIdx.x;
  if (i < N) g_counts[i] = 0;
}

__global__ void __launch_bounds__(256) hist_kernel(const int* __restrict__ ei,
                                                   int E) {
  int e = blockIdx.x * blockDim.x + threadIdx.x;
  if (e < E) atomicAdd(&g_counts[__ldg(ei + E + e)], 1);
}

__global__ void __launch_bounds__(1024) scan1_kernel(int N) {
  __shared__ int sh[1024];
  int t = threadIdx.x;
  int idx = blockIdx.x * 1024 + t;
  int v = (idx < N) ? g_counts[idx] : 0;
  sh[t] = v;
  __syncthreads();
#pragma unroll
  for (int off = 1; off < 1024; off <<= 1) {
    int x = (t >= off) ? sh[t - off] : 0;
    __syncthreads();
    sh[t] += x;
    __syncthreads();
  }
  if (idx < N) g_rowstart[idx] = sh[t] - v;
  if (t == 1023) g_blocksum[blockIdx.x] = sh[1023];
}

__global__ void __launch_bounds__(128) scan2_kernel(int nb) {
  __shared__ int sh[128];
  int t = threadIdx.x;
  int v = (t < nb) ? g_blocksum[t] : 0;
  sh[t] = v;
  __syncthreads();
#pragma unroll
  for (int off = 1; off < 128; off <<= 1) {
    int x = (t >= off) ? sh[t - off] : 0;
    __syncthreads();
    sh[t] += x;
    __syncthreads();
  }
  if (t < nb) g_blocksum[t] = sh[t] - v;
}

__global__ void __launch_bounds__(256) scan3_kernel(int N) {
  int i = blockIdx.x * blockDim.x + threadIdx.x;
  if (i < N) {
    int v = g_rowstart[i] + g_blocksum[i >> 10];
    g_rowstart[i] = v;
    g_rowend[i] = v;
  }
}

__global__ void __launch_bounds__(256) fill_kernel(const int* __restrict__ ei,
                                                   int E) {
  int e = blockIdx.x * blockDim.x + threadIdx.x;
  if (e < E) {
    int d = __ldg(ei + E + e);
    int pos = atomicAdd(&g_rowend[d], 1);
    g_csrsrc[pos] = __ldg(ei + e);
  }
}

// ---------------------------------------------------------------------------
// agg[i] = sum_{e: dst(e)=i} M[src(e)]; agg stored split (hi/lo half)
// ---------------------------------------------------------------------------
__global__ void __launch_bounds__(256) gather_kernel(int N) {
  int w = (blockIdx.x * blockDim.x + threadIdx.x) >> 5;
  int lane = threadIdx.x & 31;
  if (w >= N) return;
  int s = __ldg(&g_rowstart[w]);
  int e = __ldg(&g_rowend[w]);
  const __half2* M = (const __half2*)g_Mh4;
  float2 a0 = make_float2(0.f, 0.f), a1 = make_float2(0.f, 0.f);
  int j = s;
  for (; j + 2 <= e; j += 2) {
    int s0 = __ldg(&g_csrsrc[j]);
    int s1 = __ldg(&g_csrsrc[j + 1]);
    float2 v0 = __half22float2(__ldg(&M[(size_t)s0 * 32 + lane]));
    float2 v1 = __half22float2(__ldg(&M[(size_t)s1 * 32 + lane]));
    a0.x += v0.x; a0.y += v0.y;
    a1.x += v1.x; a1.y += v1.y;
  }
  if (j < e) {
    int s0 = __ldg(&g_csrsrc[j]);
    float2 v0 = __half22float2(__ldg(&M[(size_t)s0 * 32 + lane]));
    a0.x += v0.x; a0.y += v0.y;
  }
  float sx = a0.x + a1.x, sy = a0.y + a1.y;
  __half h0, l0, h1, l1;
  split2(sx, h0, l0);
  split2(sy, h1, l1);
  ((__half2*)g_ah4)[(size_t)w * 32 + lane] = __halves2half2(h0, h1);
  ((__half2*)g_al4)[(size_t)w * 32 + lane] = __halves2half2(l0, l1);
}

// 3-term split MMA, 32x32 warp tile (2 row frags x 2 col frags), one k chunk.
#define MMA_STEP32(APH, APL, LDAX, BPH, BPL)                                 \
  {                                                                          \
    wmma::fragment<wmma::matrix_a, 16, 16, 16, __half, wmma::row_major>    \
        ah0, ah1, al0, al1;                                                  \
    wmma::fragment<wmma::matrix_b, 16, 16, 16, __half, wmma::row_major>    \
        bh0, bh1, bl0, bl1;                                                  \
    wmma::load_matrix_sync(ah0, (APH), (LDAX));                              \
    wmma::load_matrix_sync(ah1, (APH) + 16 * (LDAX), (LDAX));                \
    wmma::load_matrix_sync(al0, (APL), (LDAX));                              \
    wmma::load_matrix_sync(al1, (APL) + 16 * (LDAX), (LDAX));                \
    wmma::load_matrix_sync(bh0, (BPH), 72);                                  \
    wmma::load_matrix_sync(bh1, (BPH) + 16, 72);                             \
    wmma::load_matrix_sync(bl0, (BPL), 72);                                  \
    wmma::load_matrix_sync(bl1, (BPL) + 16, 72);                             \
    wmma::mma_sync(acc00, ah0, bh0, acc00);                                  \
    wmma::mma_sync(acc00, al0, bh0, acc00);                                  \
    wmma::mma_sync(acc00, ah0, bl0, acc00);                                  \
    wmma::mma_sync(acc01, ah0, bh1, acc01);                                  \
    wmma::mma_sync(acc01, al0, bh1, acc01);                                  \
    wmma::mma_sync(acc01, ah0, bl1, acc01);                                  \
    wmma::mma_sync(acc10, ah1, bh0, acc10);                                  \
    wmma::mma_sync(acc10, al1, bh0, acc10);                                  \
    wmma::mma_sync(acc10, ah1, bl0, acc10);                                  \
    wmma::mma_sync(acc11, ah1, bh1, acc11);                                  \
    wmma::mma_sync(acc11, al1, bh1, acc11);                                  \
    wmma::mma_sync(acc11, ah1, bl1, acc11);                                  \
  }

#define STORE_ACC32(FSP)                                                     \
  {                                                                          \
    wmma::store_matrix_sync((FSP) + wr * 72 + wc, acc00, 72,                 \
                            wmma::mem_row_major);                            \
    wmma::store_matrix_sync((FSP) + wr * 72 + wc + 16, acc01, 72,            \
                            wmma::mem_row_major);                            \
    wmma::store_matrix_sync((FSP) + (wr + 16) * 72 + wc, acc10, 72,          \
                            wmma::mem_row_major);                            \
    wmma::store_matrix_sync((FSP) + (wr + 16) * 72 + wc + 16, acc11, 72,     \
                            wmma::mem_row_major);                            \
  }

#define FILL_ACC32()                                                         \
  {                                                                          \
    wmma::fill_fragment(acc00, 0.f);                                         \
    wmma::fill_fragment(acc01, 0.f);                                         \
    wmma::fill_fragment(acc10, 0.f);                                         \
    wmma::fill_fragment(acc11, 0.f);                                         \
  }

// ---------------------------------------------------------------------------
// msg: M = relu(h @ W1 + b1) @ W2 + b2.
// 128-row tile, 256 thr, 8 warps (4x2) each 32x32. 4 barriers.
// smem: A pair 2x(128x72), W 4x(64x72), fs 128x72 f32 = 110,592 B ->
// 2 blocks/SM.
// ---------------------------------------------------------------------------
__global__ void __launch_bounds__(256) msg_kernel(
    const __half* __restrict__ wh, const __half* __restrict__ wl,
    const float* __restrict__ B1, const float* __restrict__ B2, int N) {
  extern __shared__ char smc[];
  __half* a_hi = (__half*)smc;       // 128 x 72
  __half* a_lo = a_hi + 128 * 72;
  __half* w1h = a_lo + 128 * 72;     // 64 x 72
  __half* w1l = w1h + 64 * 72;
  __half* w2h = w1l + 64 * 72;
  __half* w2l = w2h + 64 * 72;
  float* fs = (float*)(w2l + 64 * 72);  // 128 x 72
  __shared__ float sb1[64], sb2[64];

  int tid = threadIdx.x;
  int rb = blockIdx.x * 128;

  // ---- stage (pure uint4 copies) ----
  for (int j = tid; j < 512; j += 256) {
    int k = j >> 3, ch = j & 7;
    *(uint4*)((char*)w1h + k * 144 + ch * 16) = __ldg((const uint4*)wh + j);
    *(uint4*)((char*)w1l + k * 144 + ch * 16) = __ldg((const uint4*)wl + j);
    *(uint4*)((char*)w2h + k * 144 + ch * 16) =
        __ldg((const uint4*)(wh + 4096) + j);
    *(uint4*)((char*)w2l + k * 144 + ch * 16) =
        __ldg((const uint4*)(wl + 4096) + j);
  }
  for (int j = tid; j < 1024; j += 256) {  // A hi+lo (128 rows x 8 chunks)
    int r = j >> 3, ch = j & 7;
    int grow = rb + r;
    uint4 vh = make_uint4(0, 0, 0, 0), vl = make_uint4(0, 0, 0, 0);
    if (grow < N) {
      vh = __ldg((const uint4*)((const char*)g_hh4 + (size_t)grow * 128) + ch);
      vl = __ldg((const uint4*)((const char*)g_hl4 + (size_t)grow * 128) + ch);
    }
    *(uint4*)((char*)a_hi + r * 144 + ch * 16) = vh;
    *(uint4*)((char*)a_lo + r * 144 + ch * 16) = vl;
  }
  if (tid < 64) {
    sb1[tid] = __ldg(B1 + tid);
    sb2[tid] = __ldg(B2 + tid);
  }
  __syncthreads();

  int wid = tid >> 5;
  int wr = (wid & 3) * 32, wc = (wid >> 2) * 32;

  wmma::fragment<wmma::accumulator, 16, 16, 16, float> acc00, acc01, acc10,
      acc11;
  FILL_ACC32();
#pragma unroll
  for (int k = 0; k < 64; k += 16)
    MMA_STEP32(a_hi + wr * 72 + k, a_lo + wr * 72 + k, 72, w1h + k * 72 + wc,
               w1l + k * 72 + wc);
  STORE_ACC32(fs);
  __syncthreads();

  // t = relu(fs + b1) -> a buffers (split).  128x64 elems, 32/thread.
  {
    int r = tid >> 1, c0 = (tid & 1) * 32;
#pragma unroll
    for (int q = 0; q < 8; q++) {
      int c = c0 + q * 4;
      float4 v = *(const float4*)(fs + r * 72 + c);
      float t0 = fmaxf(v.x + sb1[c + 0], 0.f);
      float t1 = fmaxf(v.y + sb1[c + 1], 0.f);
      float t2 = fmaxf(v.z + sb1[c + 2], 0.f);
      float t3 = fmaxf(v.w + sb1[c + 3], 0.f);
      __half h0, l0, h1, l1, h2, l2, h3, l3;
      split2(t0, h0, l0); split2(t1, h1, l1);
      split2(t2, h2, l2); split2(t3, h3, l3);
      *(__half2*)(a_hi + r * 72 + c) = __halves2half2(h0, h1);
      *(__half2*)(a_hi + r * 72 + c + 2) = __halves2half2(h2, h3);
      *(__half2*)(a_lo + r * 72 + c) = __halves2half2(l0, l1);
      *(__half2*)(a_lo + r * 72 + c + 2) = __halves2half2(l2, l3);
    }
  }
  __syncthreads();

  FILL_ACC32();
#pragma unroll
  for (int k = 0; k < 64; k += 16)
    MMA_STEP32(a_hi + wr * 72 + k, a_lo + wr * 72 + k, 72, w2h + k * 72 + wc,
               w2l + k * 72 + wc);
  STORE_ACC32(fs);
  __syncthreads();

  // M = fs + b2 (fp16, straight to global)
  {
    int r = tid >> 1, c0 = (tid & 1) * 32;
    int grow = rb + r;
    if (grow < N) {
      __half* mp = (__half*)g_Mh4 + (size_t)grow * 64 + c0;
#pragma unroll
      for (int q = 0; q < 8; q++) {
        int c = c0 + q * 4;
        float4 v = *(const float4*)(fs + r * 72 + c);
        *(__half2*)(mp + q * 4) =
            __floats2half2_rn(v.x + sb2[c + 0], v.y + sb2[c + 1]);
        *(__half2*)(mp + q * 4 + 2) =
            __floats2half2_rn(v.z + sb2[c + 2], v.w + sb2[c + 3]);
      }
    }
  }
}

// ---------------------------------------------------------------------------
// upd: hn = relu([h,agg] @ W1 + b1) @ W2 + b2 ; bn ; h = relu(hn + h)
// 64-row tile (as R8). Residual h_old read from smem A cols [0,64) (exact,
// still resident). 4 barriers.
// ---------------------------------------------------------------------------
__global__ void __launch_bounds__(256) upd_kernel(
    const __half* __restrict__ wh, const __half* __restrict__ wl,
    const float* __restrict__ B1, const float* __restrict__ B2,
    const float* __restrict__ Gm, const float* __restrict__ Bt,
    const float* __restrict__ Mn, const float* __restrict__ Vr, int N) {
  extern __shared__ char smc[];
  __half* a_hi = (__half*)smc;        // 64 x 136
  __half* a_lo = a_hi + 64 * 136;
  __half* w1h = a_lo + 64 * 136;      // 128 x 72
  __half* w1l = w1h + 128 * 72;
  __half* w2h = w1l + 128 * 72;       // 64 x 72
  __half* w2l = w2h + 64 * 72;
  float* fs = (float*)(w2l + 64 * 72);  // 64 x 72
  __shared__ float sb1[64], b2s[64], scs[64], shs[64];

  int tid = threadIdx.x;
  int rb = blockIdx.x * TROWS;

  // ---- stage ----
  for (int j = tid; j < 1024; j += 256) {  // W1 hi+lo (128 k-rows)
    int k = j >> 3, ch = j & 7;
    *(uint4*)((char*)w1h + k * 144 + ch * 16) = __ldg((const uint4*)wh + j);
    *(uint4*)((char*)w1l + k * 144 + ch * 16) = __ldg((const uint4*)wl + j);
  }
  for (int j = tid; j < 512; j += 256) {  // W2 hi+lo
    int k = j >> 3, ch = j & 7;
    *(uint4*)((char*)w2h + k * 144 + ch * 16) =
        __ldg((const uint4*)(wh + 8192) + j);
    *(uint4*)((char*)w2l + k * 144 + ch * 16) =
        __ldg((const uint4*)(wl + 8192) + j);
  }
  for (int j = tid; j < 512; j += 256) {  // A: h -> k cols [0,64), agg -> hi
    int r = j >> 3, ch = j & 7;
    int grow = rb + r;
    uint4 vh = make_uint4(0, 0, 0, 0), vl = make_uint4(0, 0, 0, 0);
    uint4 ah = make_uint4(0, 0, 0, 0), al = make_uint4(0, 0, 0, 0);
    if (grow < N) {
      vh = __ldg((const uint4*)((const char*)g_hh4 + (size_t)grow * 128) + ch);
      vl = __ldg((const uint4*)((const char*)g_hl4 + (size_t)grow * 128) + ch);
      ah = __ldg((const uint4*)((const char*)g_ah4 + (size_t)grow * 128) + ch);
      al = __ldg((const uint4*)((const char*)g_al4 + (size_t)grow * 128) + ch);
    }
    *(uint4*)((char*)a_hi + r * 272 + ch * 16) = vh;
    *(uint4*)((char*)a_lo + r * 272 + ch * 16) = vl;
    *(uint4*)((char*)a_hi + r * 272 + 128 + ch * 16) = ah;
    *(uint4*)((char*)a_lo + r * 272 + 128 + ch * 16) = al;
  }
  if (tid < 64) {
    float s = __ldg(Gm + tid) * rsqrtf(__ldg(Vr + tid) + 1e-5f);
    scs[tid] = s;
    shs[tid] = __ldg(Bt + tid) - __ldg(Mn + tid) * s;
    sb1[tid] = __ldg(B1 + tid);
    b2s[tid] = __ldg(B2 + tid);
  }
  __syncthreads();

  int wid = tid >> 5;
  int wr = (wid & 3) * 16, wc = (wid >> 2) * 32;

  wmma::fragment<wmma::accumulator, 16, 16, 16, float> acc0, acc1;
  wmma::fill_fragment(acc0, 0.f);
  wmma::fill_fragment(acc1, 0.f);
#pragma unroll
  for (int k = 0; k < 128; k += 16) {
    wmma::fragment<wmma::matrix_a, 16, 16, 16, __half, wmma::row_major> ah,
        al;
    wmma::fragment<wmma::matrix_b, 16, 16, 16, __half, wmma::row_major> bh0,
        bh1, bl0, bl1;
    wmma::load_matrix_sync(ah, a_hi + wr * 136 + k, 136);
    wmma::load_matrix_sync(al, a_lo + wr * 136 + k, 136);
    wmma::load_matrix_sync(bh0, w1h + k * 72 + wc, 72);
    wmma::load_matrix_sync(bh1, w1h + k * 72 + wc + 16, 72);
    wmma::load_matrix_sync(bl0, w1l + k * 72 + wc, 72);
    wmma::load_matrix_sync(bl1, w1l + k * 72 + wc + 16, 72);
    wmma::mma_sync(acc0, ah, bh0, acc0);
    wmma::mma_sync(acc0, al, bh0, acc0);
    wmma::mma_sync(acc0, ah, bl0, acc0);
    wmma::mma_sync(acc1, ah, bh1, acc1);
    wmma::mma_sync(acc1, al, bh1, acc1);
    wmma::mma_sync(acc1, ah, bl1, acc1);
  }
  wmma::store_matrix_sync(fs + wr * 72 + wc, acc0, 72, wmma::mem_row_major);
  wmma::store_matrix_sync(fs + wr * 72 + wc + 16, acc1, 72,
                          wmma::mem_row_major);
  __syncthreads();

  // t = relu(fs + b1) -> A k cols [64,128) (agg region, no longer needed)
  {
    int r = tid >> 2, c0 = (tid & 3) << 4;
#pragma unroll
    for (int q = 0; q < 4; q++) {
      int c = c0 + q * 4;
      float4 v = *(const float4*)(fs + r * 72 + c);
      float t0 = fmaxf(v.x + sb1[c + 0], 0.f);
      float t1 = fmaxf(v.y + sb1[c + 1], 0.f);
      float t2 = fmaxf(v.z + sb1[c + 2], 0.f);
      float t3 = fmaxf(v.w + sb1[c + 3], 0.f);
      __half h0, l0, h1, l1, h2, l2, h3, l3;
      split2(t0, h0, l0); split2(t1, h1, l1);
      split2(t2, h2, l2); split2(t3, h3, l3);
      *(__half2*)(a_hi + r * 136 + 64 + c) = __halves2half2(h0, h1);
      *(__half2*)(a_hi + r * 136 + 64 + c + 2) = __halves2half2(h2, h3);
      *(__half2*)(a_lo + r * 136 + 64 + c) = __halves2half2(l0, l1);
      *(__half2*)(a_lo + r * 136 + 64 + c + 2) = __halves2half2(l2, l3);
    }
  }
  __syncthreads();

  wmma::fill_fragment(acc0, 0.f);
  wmma::fill_fragment(acc1, 0.f);
#pragma unroll
  for (int k = 0; k < 64; k += 16) {
    wmma::fragment<wmma::matrix_a, 16, 16, 16, __half, wmma::row_major> ah,
        al;
    wmma::fragment<wmma::matrix_b, 16, 16, 16, __half, wmma::row_major> bh0,
        bh1, bl0, bl1;
    wmma::load_matrix_sync(ah, a_hi + wr * 136 + 64 + k, 136);
    wmma::load_matrix_sync(al, a_lo + wr * 136 + 64 + k, 136);
    wmma::load_matrix_sync(bh0, w2h + k * 72 + wc, 72);
    wmma::load_matrix_sync(bh1, w2h + k * 72 + wc + 16, 72);
    wmma::load_matrix_sync(bl0, w2l + k * 72 + wc, 72);
    wmma::load_matrix_sync(bl1, w2l + k * 72 + wc + 16, 72);
    wmma::mma_sync(acc0, ah, bh0, acc0);
    wmma::mma_sync(acc0, al, bh0, acc0);
    wmma::mma_sync(acc0, ah, bl0, acc0);
    wmma::mma_sync(acc1, ah, bh1, acc1);
    wmma::mma_sync(acc1, al, bh1, acc1);
    wmma::mma_sync(acc1, ah, bl1, acc1);
  }
  wmma::store_matrix_sync(fs + wr * 72 + wc, acc0, 72, wmma::mem_row_major);
  wmma::store_matrix_sync(fs + wr * 72 + wc + 16, acc1, 72,
                          wmma::mem_row_major);
  __syncthreads();

  // h = relu(bn(fs + b2) + h_old); h_old = hi+lo from smem A cols [0,64)
  {
    int r = tid >> 2, c0 = (tid & 3) << 4;
    int grow = rb + r;
    if (grow < N) {
      __half2 oh[8], ol[8];
#pragma unroll
      for (int q = 0; q < 8; q++) {
        int c = c0 + 2 * q;
        float2 hi2 = __half22float2(*(const __half2*)(a_hi + r * 136 + c));
        float2 lo2 = __half22float2(*(const __half2*)(a_lo + r * 136 + c));
        float v0 = fs[r * 72 + c] + b2s[c];
        float v1 = fs[r * 72 + c + 1] + b2s[c + 1];
        float o0 = fmaxf(fmaf(v0, scs[c], shs[c]) + hi2.x + lo2.x, 0.f);
        float o1 = fmaxf(fmaf(v1, scs[c + 1], shs[c + 1]) + hi2.y + lo2.y,
                         0.f);
        __half h0, l0, h1, l1;
        split2(o0, h0, l0);
        split2(o1, h1, l1);
        oh[q] = __halves2half2(h0, h1);
        ol[q] = __halves2half2(l0, l1);
      }
      __half2* dh = (__half2*)((char*)g_hh4 + (size_t)grow * 128 + c0 * 2);
      __half2* dl = (__half2*)((char*)g_hl4 + (size_t)grow * 128 + c0 * 2);
#pragma unroll
      for (int q = 0; q < 8; q++) {
        dh[q] = oh[q];
        dl[q] = ol[q];
      }
    }
  }
}

// ---------------------------------------------------------------------------
// out = relu(h[:NQ] @ out_w1 + b1) @ out_w2 + b2   (warp per node)
// ---------------------------------------------------------------------------
__global__ void __launch_bounds__(256) out_kernel(
    const float* __restrict__ w1, const float* __restrict__ b1,
    const float* __restrict__ w2, const float* __restrict__ b2,
    float* __restrict__ out, int NQ) {
  int warp = (blockIdx.x * blockDim.x + threadIdx.x) >> 5;
  int lane = threadIdx.x & 31;
  if (warp >= NQ) return;
  float2 hh = __half22float2(((const __half2*)g_hh4)[(size_t)warp * 32 + lane]);
  float2 hl = __half22float2(((const __half2*)g_hl4)[(size_t)warp * 32 + lane]);
  float2 hv = make_float2(hh.x + hl.x, hh.y + hl.y);
  float acc = __ldg(b1 + lane);
#pragma unroll
  for (int kk = 0; kk < 32; kk++) {
    float hx = __shfl_sync(0xffffffffu, hv.x, kk);
    float hy = __shfl_sync(0xffffffffu, hv.y, kk);
    acc = fmaf(hx, __ldg(w1 + (2 * kk) * 32 + lane), acc);
    acc = fmaf(hy, __ldg(w1 + (2 * kk + 1) * 32 + lane), acc);
  }
  float v = fmaxf(acc, 0.f) * __ldg(w2 + lane);
#pragma unroll
  for (int o = 16; o; o >>= 1) v += __shfl_down_sync(0xffffffffu, v, o);
  if (lane == 0) out[warp] = v + __ldg(b2);
}

// ---------------------------------------------------------------------------
extern "C" void kernel_launch(void* const* d_in, const int* in_sizes, int n_in,
                              void* d_out, int out_size) {
  int off = (n_in >= 21) ? 1 : 0;
  const float* x      = (const float*)d_in[0];
  const int*   ei     = (const int*)d_in[1];
  const float* w_in   = (const float*)d_in[2 + off];
  const float* b_in   = (const float*)d_in[3 + off];
  const float* msg_w1 = (const float*)d_in[4 + off];
  const float* msg_b1 = (const float*)d_in[5 + off];
  const float* msg_w2 = (const float*)d_in[6 + off];
  const float* msg_b2 = (const float*)d_in[7 + off];
  const float* upd_w1 = (const float*)d_in[8 + off];
  const float* upd_b1 = (const float*)d_in[9 + off];
  const float* upd_w2 = (const float*)d_in[10 + off];
  const float* upd_b2 = (const float*)d_in[11 + off];
  const float* bn_g   = (const float*)d_in[12 + off];
  const float* bn_b   = (const float*)d_in[13 + off];
  const float* bn_m   = (const float*)d_in[14 + off];
  const float* bn_v   = (const float*)d_in[15 + off];
  const float* out_w1 = (const float*)d_in[16 + off];
  const float* out_b1 = (const float*)d_in[17 + off];
  const float* out_w2 = (const float*)d_in[18 + off];
  const float* out_b2 = (const float*)d_in[19 + off];

  int N = in_sizes[0] / 3;
  int E = in_sizes[1] / 2;
  int L = in_sizes[4 + off] / (64 * 64);
  int NQ = out_size;

  const int MSG_SMEM =
      (2 * 128 * 72 + 4 * 64 * 72) * 2 + 128 * 72 * 4;  // 110,592 B
  const int UPD_SMEM =
      (2 * 64 * 136 + 2 * 128 * 72 + 2 * 64 * 72) * 2 + 64 * 72 * 4;  // 108,544
  cudaFuncSetAttribute(msg_kernel, cudaFuncAttributeMaxDynamicSharedMemorySize,
                       MSG_SMEM);
  cudaFuncSetAttribute(upd_kernel, cudaFuncAttributeMaxDynamicSharedMemorySize,
                       UPD_SMEM);

  int gbm = (N + 127) / 128;
  int gbu = (N + TROWS - 1) / TROWS;
  int nb_scan = (N + 1023) / 1024;

  void* whp = nullptr;
  void* wlp = nullptr;
  cudaGetSymbolAddress(&whp, g_wh4);
  cudaGetSymbolAddress(&wlp, g_wl4);
  const __half* wh = (const __half*)whp;
  const __half* wl = (const __half*)wlp;

  // Order: wprep(1), input(2), zero(3), msg0(4) <- profiled slot, hist(5)...
  wprep_kernel<<<(L * 20480 + 255) / 256, 256>>>(msg_w1, msg_w2, upd_w1,
                                                 upd_w2, L);
  input_kernel<<<(N * 64 + 255) / 256, 256>>>(x, w_in, b_in, N);
  zero_counts_kernel<<<(N + 255) / 256, 256>>>(N);
  msg_kernel<<<gbm, 256, MSG_SMEM>>>(wh, wl, msg_b1, msg_b2, N);
  hist_kernel<<<(E + 255) / 256, 256>>>(ei, E);
  scan1_kernel<<<nb_scan, 1024>>>(N);
  scan2_kernel<<<1, 128>>>(nb_scan);
  scan3_kernel<<<(N + 255) / 256, 256>>>(N);
  fill_kernel<<<(E + 255) / 256, 256>>>(ei, E);

  for (int l = 0; l < L; l++) {
    if (l > 0)
      msg_kernel<<<gbm, 256, MSG_SMEM>>>(wh + l * 20480, wl + l * 20480,
                                         msg_b1 + l * 64, msg_b2 + l * 64, N);
    gather_kernel<<<(N * 32 + 255) / 256, 256>>>(N);
    upd_kernel<<<gbu, 256, UPD_SMEM>>>(
        wh + l * 20480 + 8192, wl + l * 20480 + 8192, upd_b1 + l * 64,
        upd_b2 + l * 64, bn_g + l * 64, bn_b + l * 64, bn_m + l * 64,
        bn_v + l * 64, N);
  }

  out_kernel<<<(NQ * 32 + 255) / 256, 256>>>(out_w1, out_b1, out_w2, out_b2,
                                             (float*)d_out, NQ);
}